// round 13
// baseline (speedup 1.0000x reference)
#include <cuda_runtime.h>
#include <cuda_bf16.h>
#include <math_constants.h>
#include <cstdint>

#define Nn 50000
#define En 500000
#define IN_DIM 128
#define Hh 8
#define HD 256
#define PERMD 100
#define Bb 64
#define Cc 10
#define SLOPE 0.2f
#define NPART 16

// ---------------- scratch (static device globals) --------------------------
__device__ __nv_bfloat16 g_zh[(size_t)Nn * HD];   // z (bf16) for edge gather
__device__ __nv_bfloat16 g_h1h[(size_t)Nn * HD];  // layer-1 output (bf16, relu'd)
__device__ float g_el[Nn * Hh];
__device__ float g_er[Nn * Hh];
__device__ int   g_rowoff[Nn + 1];
__device__ int   g_cursor[Nn];
__device__ int   g_esrc[En];                      // src node of each CSR slot
__device__ int   g_bsum[64];
__device__ int   g_gbound[Bb + 1];
__device__ float g_hgp[NPART * Bb * HD];          // partial graph sums
__device__ float g_hg[Bb * HD];                   // reduced graph means

// ---------------- CSR build ------------------------------------------------
__global__ void k_zero_counts() {
    int i = blockIdx.x * blockDim.x + threadIdx.x;
    if (i < Nn) g_cursor[i] = 0;
}

__global__ void k_count(const int* __restrict__ dstv) {
    int e = blockIdx.x * blockDim.x + threadIdx.x;
    if (e < En) atomicAdd(&g_cursor[dstv[e]], 1);
}

// per-1024-chunk sums (49 blocks)
__global__ void k_bsum() {
    __shared__ int wsum[32];
    int t = threadIdx.x, b = blockIdx.x;
    int i = b * 1024 + t;
    int v = (i < Nn) ? g_cursor[i] : 0;
    #pragma unroll
    for (int off = 16; off; off >>= 1) v += __shfl_xor_sync(0xFFFFFFFFu, v, off);
    if ((t & 31) == 0) wsum[t >> 5] = v;
    __syncthreads();
    if (t < 32) {
        int s = wsum[t];
        #pragma unroll
        for (int off = 16; off; off >>= 1) s += __shfl_xor_sync(0xFFFFFFFFu, s, off);
        if (t == 0) g_bsum[b] = s;
    }
}

// parallel block-scan: carry from preceding block sums, local scan, write out
__global__ void k_scan2() {
    __shared__ int wsum[32];
    __shared__ int carry_s;
    int t = threadIdx.x, b = blockIdx.x;
    int lane = t & 31, wid = t >> 5;
    if (t < 32) {
        int c = (t < b) ? g_bsum[t] : 0;
        if (t + 32 < b) c += g_bsum[t + 32];
        #pragma unroll
        for (int off = 16; off; off >>= 1) c += __shfl_xor_sync(0xFFFFFFFFu, c, off);
        if (t == 0) carry_s = c;
    }
    int i = b * 1024 + t;
    int v = (i < Nn) ? g_cursor[i] : 0;
    int incl = v;
    #pragma unroll
    for (int off = 1; off < 32; off <<= 1) {
        int tv = __shfl_up_sync(0xFFFFFFFFu, incl, off);
        if (lane >= off) incl += tv;
    }
    if (lane == 31) wsum[wid] = incl;
    __syncthreads();
    if (wid == 0) {
        int s = wsum[lane];
        #pragma unroll
        for (int off = 1; off < 32; off <<= 1) {
            int tv = __shfl_up_sync(0xFFFFFFFFu, s, off);
            if (lane >= off) s += tv;
        }
        wsum[lane] = s;
    }
    __syncthreads();
    int woff = (wid > 0) ? wsum[wid - 1] : 0;
    int excl = carry_s + woff + incl - v;
    if (i < Nn) {
        g_rowoff[i] = excl;
        g_cursor[i] = excl;
    }
    if (b == 0 && t == 0) g_rowoff[Nn] = En;
}

__global__ void k_scatter(const int* __restrict__ srcv, const int* __restrict__ dstv) {
    int e = blockIdx.x * blockDim.x + threadIdx.x;
    if (e < En) {
        int p = atomicAdd(&g_cursor[dstv[e]], 1);
        g_esrc[p] = srcv[e];
    }
}

// ---------------- bf16 tensor-core GEMM (ldmatrix + m16n8k16) --------------
// ASEL=0: A is fp32 external (converted on load). ASEL=1: A is bf16 g_h1h.
__device__ __forceinline__ void mma_bf16(float* c, const uint32_t* a,
                                         uint32_t b0, uint32_t b1) {
    asm volatile(
        "mma.sync.aligned.m16n8k16.row.col.f32.bf16.bf16.f32 "
        "{%0,%1,%2,%3}, {%4,%5,%6,%7}, {%8,%9}, {%0,%1,%2,%3};"
        : "+f"(c[0]), "+f"(c[1]), "+f"(c[2]), "+f"(c[3])
        : "r"(a[0]), "r"(a[1]), "r"(a[2]), "r"(a[3]), "r"(b0), "r"(b1));
}

__device__ __forceinline__ void ldsm_x4(uint32_t* r, uint32_t addr) {
    asm volatile("ldmatrix.sync.aligned.m8n8.x4.shared.b16 {%0,%1,%2,%3}, [%4];"
                 : "=r"(r[0]), "=r"(r[1]), "=r"(r[2]), "=r"(r[3]) : "r"(addr));
}

__device__ __forceinline__ void ldsm_x2t(uint32_t& r0, uint32_t& r1, uint32_t addr) {
    asm volatile("ldmatrix.sync.aligned.m8n8.x2.trans.shared.b16 {%0,%1}, [%2];"
                 : "=r"(r0), "=r"(r1) : "r"(addr));
}

template <int ASEL>
__global__ __launch_bounds__(256, 2) void k_gemm_bf16(const float* __restrict__ Aext,
                                                      const float* __restrict__ W,
                                                      const float* __restrict__ al,
                                                      const float* __restrict__ ar,
                                                      int K) {
    __shared__ __nv_bfloat16 As[128][40];    // [m][k], stride 20 words: CF ldmatrix
    __shared__ __nv_bfloat16 Bs[32][136];    // [k][n], stride 68 words: CF ldmatrix
    int tid = threadIdx.x;
    int lane = tid & 31, wid = tid >> 5;
    int wm = wid & 3, wn = wid >> 2;          // 4 warps along M, 2 along N
    int row0 = blockIdx.y * 128, col0 = blockIdx.x * 128;
    int lr = lane >> 2, lc = lane & 3;

    uint32_t sA = (uint32_t)__cvta_generic_to_shared(&As[0][0]);
    uint32_t sB = (uint32_t)__cvta_generic_to_shared(&Bs[0][0]);

    float acc[2][8][4];
    #pragma unroll
    for (int mt = 0; mt < 2; mt++)
        #pragma unroll
        for (int nt = 0; nt < 8; nt++)
            #pragma unroll
            for (int j = 0; j < 4; j++) acc[mt][nt][j] = 0.f;

    uint32_t aAddrBase[2];
    #pragma unroll
    for (int mt = 0; mt < 2; mt++) {
        int m = wm * 32 + mt * 16 + (lane & 15);
        aAddrBase[mt] = sA + (uint32_t)(m * 80 + ((lane >> 4) << 4));
    }
    uint32_t bAddrBase = sB + (uint32_t)(((lane & 7) + ((lane >> 3) & 1) * 8) * 272);

    float4 paf[4];
    uint4  pau[2];
    float4 pb[4];

    if constexpr (ASEL == 0) {
        #pragma unroll
        for (int r = 0; r < 4; r++) {
            int idx = r * 256 + tid;
            int row = idx >> 3, c4 = (idx & 7) * 4;
            int gr = row0 + row;
            paf[r] = make_float4(0.f, 0.f, 0.f, 0.f);
            if (gr < Nn) paf[r] = *(const float4*)(Aext + (size_t)gr * K + c4);
        }
    } else {
        #pragma unroll
        for (int r = 0; r < 2; r++) {
            int idx = r * 256 + tid;
            int row = idx >> 2, c8 = (idx & 3) * 8;
            int gr = row0 + row;
            pau[r] = make_uint4(0u, 0u, 0u, 0u);
            if (gr < Nn) pau[r] = *(const uint4*)(g_h1h + (size_t)gr * K + c8);
        }
    }
    #pragma unroll
    for (int r = 0; r < 4; r++) {
        int idx = r * 256 + tid;
        int kr = idx >> 5, c4 = (idx & 31) * 4;
        pb[r] = *(const float4*)(W + (size_t)kr * HD + col0 + c4);
    }

    for (int k0 = 0; k0 < K; k0 += 32) {
        if constexpr (ASEL == 0) {
            #pragma unroll
            for (int r = 0; r < 4; r++) {
                int idx = r * 256 + tid;
                int row = idx >> 3, c4 = (idx & 7) * 4;
                __nv_bfloat162 p0 = __float22bfloat162_rn(make_float2(paf[r].x, paf[r].y));
                __nv_bfloat162 p1 = __float22bfloat162_rn(make_float2(paf[r].z, paf[r].w));
                uint2 u;
                u.x = *(uint32_t*)&p0; u.y = *(uint32_t*)&p1;
                *(uint2*)&As[row][c4] = u;
            }
        } else {
            #pragma unroll
            for (int r = 0; r < 2; r++) {
                int idx = r * 256 + tid;
                int row = idx >> 2, c8 = (idx & 3) * 8;
                *(uint4*)&As[row][c8] = pau[r];
            }
        }
        #pragma unroll
        for (int r = 0; r < 4; r++) {
            int idx = r * 256 + tid;
            int kr = idx >> 5, c4 = (idx & 31) * 4;
            __nv_bfloat162 p0 = __float22bfloat162_rn(make_float2(pb[r].x, pb[r].y));
            __nv_bfloat162 p1 = __float22bfloat162_rn(make_float2(pb[r].z, pb[r].w));
            uint2 u;
            u.x = *(uint32_t*)&p0; u.y = *(uint32_t*)&p1;
            *(uint2*)&Bs[kr][c4] = u;
        }
        __syncthreads();

        int kn = k0 + 32;
        if (kn < K) {
            if constexpr (ASEL == 0) {
                #pragma unroll
                for (int r = 0; r < 4; r++) {
                    int idx = r * 256 + tid;
                    int row = idx >> 3, c4 = (idx & 7) * 4;
                    int gr = row0 + row;
                    paf[r] = make_float4(0.f, 0.f, 0.f, 0.f);
                    if (gr < Nn) paf[r] = *(const float4*)(Aext + (size_t)gr * K + kn + c4);
                }
            } else {
                #pragma unroll
                for (int r = 0; r < 2; r++) {
                    int idx = r * 256 + tid;
                    int row = idx >> 2, c8 = (idx & 3) * 8;
                    int gr = row0 + row;
                    pau[r] = make_uint4(0u, 0u, 0u, 0u);
                    if (gr < Nn) pau[r] = *(const uint4*)(g_h1h + (size_t)gr * K + kn + c8);
                }
            }
            #pragma unroll
            for (int r = 0; r < 4; r++) {
                int idx = r * 256 + tid;
                int kr = idx >> 5, c4 = (idx & 31) * 4;
                pb[r] = *(const float4*)(W + (size_t)(kn + kr) * HD + col0 + c4);
            }
        }

        #pragma unroll
        for (int ks = 0; ks < 2; ks++) {
            uint32_t a[2][4];
            #pragma unroll
            for (int mt = 0; mt < 2; mt++)
                ldsm_x4(a[mt], aAddrBase[mt] + ks * 32);
            #pragma unroll
            for (int nt = 0; nt < 8; nt++) {
                int nb = wn * 64 + nt * 8;
                uint32_t b0, b1;
                ldsm_x2t(b0, b1, bAddrBase + (uint32_t)(ks * 16 * 272 + nb * 2));
                #pragma unroll
                for (int mt = 0; mt < 2; mt++)
                    mma_bf16(acc[mt][nt], a[mt], b0, b1);
            }
        }
        __syncthreads();
    }

    // ---- store z as bf16 ----
    #pragma unroll
    for (int mt = 0; mt < 2; mt++) {
        #pragma unroll
        for (int nt = 0; nt < 8; nt++) {
            int r = row0 + wm * 32 + mt * 16 + lr;
            int c = col0 + wn * 64 + nt * 8 + lc * 2;
            if (r < Nn)
                *(__nv_bfloat162*)&g_zh[(size_t)r * HD + c] =
                    __float22bfloat162_rn(make_float2(acc[mt][nt][0], acc[mt][nt][1]));
            if (r + 8 < Nn)
                *(__nv_bfloat162*)&g_zh[(size_t)(r + 8) * HD + c] =
                    __float22bfloat162_rn(make_float2(acc[mt][nt][2], acc[mt][nt][3]));
        }
    }

    // ---- fused el/er ----
    int head_base = (col0 >> 5) + wn * 2;
    float alc[2][8], arc[2][8];
    #pragma unroll
    for (int hs = 0; hs < 2; hs++)
        #pragma unroll
        for (int q = 0; q < 4; q++) {
            int d0 = q * 8 + lc * 2;
            int hg = head_base + hs;
            alc[hs][q * 2]     = al[hg * 32 + d0];
            alc[hs][q * 2 + 1] = al[hg * 32 + d0 + 1];
            arc[hs][q * 2]     = ar[hg * 32 + d0];
            arc[hs][q * 2 + 1] = ar[hg * 32 + d0 + 1];
        }
    float pel[4][2], per_[4][2];
    #pragma unroll
    for (int rs = 0; rs < 4; rs++)
        #pragma unroll
        for (int hs = 0; hs < 2; hs++) { pel[rs][hs] = 0.f; per_[rs][hs] = 0.f; }
    #pragma unroll
    for (int mt = 0; mt < 2; mt++)
        #pragma unroll
        for (int nt = 0; nt < 8; nt++) {
            int hs = nt >> 2, q = nt & 3;
            #pragma unroll
            for (int j = 0; j < 4; j++) {
                int rs = mt * 2 + (j >> 1);
                float a = acc[mt][nt][j];
                pel[rs][hs]  = fmaf(a, alc[hs][q * 2 + (j & 1)], pel[rs][hs]);
                per_[rs][hs] = fmaf(a, arc[hs][q * 2 + (j & 1)], per_[rs][hs]);
            }
        }
    #pragma unroll
    for (int rs = 0; rs < 4; rs++)
        #pragma unroll
        for (int hs = 0; hs < 2; hs++) {
            float v = pel[rs][hs], w = per_[rs][hs];
            v += __shfl_xor_sync(0xFFFFFFFFu, v, 1);
            v += __shfl_xor_sync(0xFFFFFFFFu, v, 2);
            w += __shfl_xor_sync(0xFFFFFFFFu, w, 1);
            w += __shfl_xor_sync(0xFFFFFFFFu, w, 2);
            if (lc == 0) {
                int r = row0 + wm * 32 + (rs >> 1) * 16 + (rs & 1) * 8 + lr;
                if (r < Nn) {
                    g_el[r * 8 + head_base + hs] = v;
                    g_er[r * 8 + head_base + hs] = w;
                }
            }
        }
}

// ------- warp-per-node aggregation: smem-staged weights, 2-edge unroll -----
// out_sel=1: write bf16 h1 (+relu). out_sel=0: atomic-add into graph partials.
__global__ __launch_bounds__(256) void k_agg(const float* __restrict__ bias,
                                             const int* __restrict__ gid,
                                             int out_sel) {
    __shared__ float sw[8][32][8];
    int gw = (blockIdx.x * blockDim.x + threadIdx.x) >> 5;
    if (gw >= Nn) return;
    int lane = threadIdx.x & 31;
    int wloc = threadIdx.x >> 5;
    int s0 = g_rowoff[gw], s1 = g_rowoff[gw + 1];

    float acc[8];
    #pragma unroll
    for (int k = 0; k < 8; k++) acc[k] = 0.f;
    float smv = 0.f;

    if (s1 > s0) {
        float4 erA = *(const float4*)(g_er + (size_t)gw * 8);
        float4 erB = *(const float4*)(g_er + (size_t)gw * 8 + 4);
        float er8[8] = {erA.x, erA.y, erA.z, erA.w, erB.x, erB.y, erB.z, erB.w};

        for (int base = s0; base < s1; base += 32) {
            int idx = base + lane;
            int cnt = min(32, s1 - base);
            int sn_l = (idx < s1) ? g_esrc[idx] : 0;
            if (idx < s1) {
                float4 e0 = *(const float4*)(g_el + (size_t)sn_l * 8);
                float4 e1 = *(const float4*)(g_el + (size_t)sn_l * 8 + 4);
                float ev[8] = {e0.x + er8[0], e0.y + er8[1], e0.z + er8[2], e0.w + er8[3],
                               e1.x + er8[4], e1.y + er8[5], e1.z + er8[6], e1.w + er8[7]};
                float wv[8];
                #pragma unroll
                for (int k = 0; k < 8; k++) {
                    float t = ev[k] > 0.f ? ev[k] : SLOPE * ev[k];
                    wv[k] = __expf(t);
                }
                *(float4*)&sw[wloc][lane][0] = make_float4(wv[0], wv[1], wv[2], wv[3]);
                *(float4*)&sw[wloc][lane][4] = make_float4(wv[4], wv[5], wv[6], wv[7]);
            }
            __syncwarp();
            int hsel = lane >> 2;
            int j = 0;
            for (; j + 2 <= cnt; j += 2) {
                int sn0 = __shfl_sync(0xFFFFFFFFu, sn_l, j);
                int sn1 = __shfl_sync(0xFFFFFFFFu, sn_l, j + 1);
                float w0 = sw[wloc][j][hsel];
                float w1 = sw[wloc][j + 1][hsel];
                uint4 r0 = *(const uint4*)(g_zh + (size_t)sn0 * HD + lane * 8);
                uint4 r1 = *(const uint4*)(g_zh + (size_t)sn1 * HD + lane * 8);
                smv += w0 + w1;
                float2 a0 = __bfloat1622float2(*(__nv_bfloat162*)&r0.x);
                float2 a1 = __bfloat1622float2(*(__nv_bfloat162*)&r0.y);
                float2 a2 = __bfloat1622float2(*(__nv_bfloat162*)&r0.z);
                float2 a3 = __bfloat1622float2(*(__nv_bfloat162*)&r0.w);
                acc[0] = fmaf(w0, a0.x, acc[0]); acc[1] = fmaf(w0, a0.y, acc[1]);
                acc[2] = fmaf(w0, a1.x, acc[2]); acc[3] = fmaf(w0, a1.y, acc[3]);
                acc[4] = fmaf(w0, a2.x, acc[4]); acc[5] = fmaf(w0, a2.y, acc[5]);
                acc[6] = fmaf(w0, a3.x, acc[6]); acc[7] = fmaf(w0, a3.y, acc[7]);
                float2 b0 = __bfloat1622float2(*(__nv_bfloat162*)&r1.x);
                float2 b1 = __bfloat1622float2(*(__nv_bfloat162*)&r1.y);
                float2 b2 = __bfloat1622float2(*(__nv_bfloat162*)&r1.z);
                float2 b3 = __bfloat1622float2(*(__nv_bfloat162*)&r1.w);
                acc[0] = fmaf(w1, b0.x, acc[0]); acc[1] = fmaf(w1, b0.y, acc[1]);
                acc[2] = fmaf(w1, b1.x, acc[2]); acc[3] = fmaf(w1, b1.y, acc[3]);
                acc[4] = fmaf(w1, b2.x, acc[4]); acc[5] = fmaf(w1, b2.y, acc[5]);
                acc[6] = fmaf(w1, b3.x, acc[6]); acc[7] = fmaf(w1, b3.y, acc[7]);
            }
            if (j < cnt) {
                int sn = __shfl_sync(0xFFFFFFFFu, sn_l, j);
                float wv = sw[wloc][j][hsel];
                smv += wv;
                uint4 raw = *(const uint4*)(g_zh + (size_t)sn * HD + lane * 8);
                float2 f0 = __bfloat1622float2(*(__nv_bfloat162*)&raw.x);
                float2 f1 = __bfloat1622float2(*(__nv_bfloat162*)&raw.y);
                float2 f2 = __bfloat1622float2(*(__nv_bfloat162*)&raw.z);
                float2 f3 = __bfloat1622float2(*(__nv_bfloat162*)&raw.w);
                acc[0] = fmaf(wv, f0.x, acc[0]); acc[1] = fmaf(wv, f0.y, acc[1]);
                acc[2] = fmaf(wv, f1.x, acc[2]); acc[3] = fmaf(wv, f1.y, acc[3]);
                acc[4] = fmaf(wv, f2.x, acc[4]); acc[5] = fmaf(wv, f2.y, acc[5]);
                acc[6] = fmaf(wv, f3.x, acc[6]); acc[7] = fmaf(wv, f3.y, acc[7]);
            }
            __syncwarp();
        }
        float inv = __frcp_rn(smv);
        #pragma unroll
        for (int k = 0; k < 8; k++) acc[k] *= inv;
    }

    const float* bp = bias + lane * 8;
    float o[8];
    #pragma unroll
    for (int k = 0; k < 8; k++) o[k] = acc[k] + bp[k];

    if (out_sel) {
        // layer 1: relu + bf16 store
        #pragma unroll
        for (int k = 0; k < 8; k++) o[k] = fmaxf(o[k], 0.f);
        __nv_bfloat162 q0 = __float22bfloat162_rn(make_float2(o[0], o[1]));
        __nv_bfloat162 q1 = __float22bfloat162_rn(make_float2(o[2], o[3]));
        __nv_bfloat162 q2 = __float22bfloat162_rn(make_float2(o[4], o[5]));
        __nv_bfloat162 q3 = __float22bfloat162_rn(make_float2(o[6], o[7]));
        uint4 u;
        u.x = *(uint32_t*)&q0; u.y = *(uint32_t*)&q1;
        u.z = *(uint32_t*)&q2; u.w = *(uint32_t*)&q3;
        *(uint4*)(g_h1h + (size_t)gw * HD + lane * 8) = u;
    } else {
        // layer 2: accumulate h2 directly into per-graph partial sums
        int b = gid[gw];
        float* dst = g_hgp + (size_t)(gw & (NPART - 1)) * (Bb * HD)
                     + b * HD + lane * 8;
        #pragma unroll
        for (int k = 0; k < 8; k++) atomicAdd(dst + k, o[k]);
    }
}

// ---------------- readout --------------------------------------------------
// zero partials + compute graph boundaries (side stream)
__global__ void k_gbound_zero(const int* __restrict__ gid) {
    int t = blockIdx.x * blockDim.x + threadIdx.x;
    if (t < NPART * Bb * HD) g_hgp[t] = 0.f;
    if (blockIdx.x == 0 && threadIdx.x <= Bb) {
        int g = threadIdx.x;
        int lo = 0, hi = Nn;
        while (lo < hi) {
            int mid = (lo + hi) >> 1;
            if (gid[mid] < g) lo = mid + 1;
            else hi = mid;
        }
        g_gbound[g] = lo;
    }
}

// reduce NPART partials -> mean
__global__ void k_hgred() {
    int t = blockIdx.x * blockDim.x + threadIdx.x;
    if (t >= Bb * HD) return;
    int b = t / HD;
    float sum = 0.f;
    #pragma unroll
    for (int p = 0; p < NPART; p++) sum += g_hgp[(size_t)p * (Bb * HD) + t];
    int cnt = g_gbound[b + 1] - g_gbound[b];
    g_hg[t] = sum / (float)(cnt > 0 ? cnt : 1);
}

__global__ void k_cls(const float* __restrict__ perm, const float* __restrict__ Wc,
                      const float* __restrict__ bc, float* __restrict__ out) {
    int t = blockIdx.x * blockDim.x + threadIdx.x;
    if (t >= Bb * Cc) return;
    int b = t / Cc, c = t % Cc;
    float s = bc[c];
    #pragma unroll 4
    for (int i = 0; i < HD; i++) s = fmaf(g_hg[b * HD + i], Wc[i * Cc + c], s);
    #pragma unroll 4
    for (int i = 0; i < PERMD; i++)
        s = fmaf(perm[b * PERMD + i], Wc[(HD + i) * Cc + c], s);
    out[t] = s;
}

// ---------------- launch: fork CSR chain onto a side stream ----------------
extern "C" void kernel_launch(void* const* d_in, const int* in_sizes, int n_in,
                              void* d_out, int out_size) {
    const float* h    = (const float*)d_in[0];
    const float* perm = (const float*)d_in[1];
    const float* W1   = (const float*)d_in[2];
    const float* al1  = (const float*)d_in[3];
    const float* ar1  = (const float*)d_in[4];
    const float* b1   = (const float*)d_in[5];
    const float* W2   = (const float*)d_in[6];
    const float* al2  = (const float*)d_in[7];
    const float* ar2  = (const float*)d_in[8];
    const float* b2   = (const float*)d_in[9];
    const float* Wc   = (const float*)d_in[10];
    const float* bc   = (const float*)d_in[11];
    const int*   src  = (const int*)d_in[12];
    const int*   dstv = (const int*)d_in[13];
    const int*   gid  = (const int*)d_in[14];
    float* out = (float*)d_out;

    cudaStream_t s0 = (cudaStream_t)0;       // capture-origin (legacy) stream
    cudaStream_t s2;
    cudaStreamCreateWithFlags(&s2, cudaStreamNonBlocking);
    cudaEvent_t eFork, eCsr, eGb;
    cudaEventCreateWithFlags(&eFork, cudaEventDisableTiming);
    cudaEventCreateWithFlags(&eCsr, cudaEventDisableTiming);
    cudaEventCreateWithFlags(&eGb, cudaEventDisableTiming);

    // fork side stream off the origin stream (capture-legal pattern)
    cudaEventRecord(eFork, s0);
    cudaStreamWaitEvent(s2, eFork, 0);

    // side stream: CSR build + graph boundaries + partial-buffer zero
    k_zero_counts<<<(Nn + 255) / 256, 256, 0, s2>>>();
    k_count<<<(En + 255) / 256, 256, 0, s2>>>(dstv);
    k_bsum<<<49, 1024, 0, s2>>>();
    k_scan2<<<49, 1024, 0, s2>>>();
    k_scatter<<<(En + 255) / 256, 256, 0, s2>>>(src, dstv);
    cudaEventRecord(eCsr, s2);
    k_gbound_zero<<<(NPART * Bb * HD + 255) / 256, 256, 0, s2>>>(gid);
    cudaEventRecord(eGb, s2);

    dim3 gemm_grid(HD / 128, (Nn + 127) / 128);
    int node_warp_blocks = (Nn * 32 + 255) / 256;

    // main stream: layer-1 GEMM overlaps CSR build
    k_gemm_bf16<0><<<gemm_grid, 256, 0, s0>>>(h, W1, al1, ar1, IN_DIM);
    cudaStreamWaitEvent(s0, eCsr, 0);        // join: agg needs rowoff/esrc
    k_agg<<<node_warp_blocks, 256, 0, s0>>>(b1, gid, /*out=h1 bf16*/1);

    // layer 2 (A = bf16 g_h1h); agg2 accumulates graph partials directly
    k_gemm_bf16<1><<<gemm_grid, 256, 0, s0>>>(nullptr, W2, al2, ar2, HD);
    cudaStreamWaitEvent(s0, eGb, 0);         // join: partials zeroed, gbound ready
    k_agg<<<node_warp_blocks, 256, 0, s0>>>(b2, gid, /*graph partials*/0);

    // readout
    k_hgred<<<(Bb * HD + 255) / 256, 256, 0, s0>>>();
    k_cls<<<(Bb * Cc + 127) / 128, 128, 0, s0>>>(perm, Wc, bc, out);

    cudaEventDestroy(eFork);
    cudaEventDestroy(eCsr);
    cudaEventDestroy(eGb);
    cudaStreamDestroy(s2);
}

// round 14
// speedup vs baseline: 1.4118x; 1.4118x over previous
#include <cuda_runtime.h>
#include <cuda_bf16.h>
#include <math_constants.h>
#include <cstdint>

#define Nn 50000
#define En 500000
#define IN_DIM 128
#define Hh 8
#define HD 256
#define PERMD 100
#define Bb 64
#define Cc 10
#define SLOPE 0.2f

// ---------------- scratch (static device globals) --------------------------
__device__ __nv_bfloat16 g_zh[(size_t)Nn * HD];   // z (bf16) for edge gather
__device__ __nv_bfloat16 g_h1h[(size_t)Nn * HD];  // layer-1 output (bf16, relu'd)
__device__ __nv_bfloat16 g_h2h[(size_t)Nn * HD];  // layer-2 output (bf16, for mean)
__device__ float g_el[Nn * Hh];
__device__ float g_er[Nn * Hh];
__device__ int   g_rowoff[Nn + 1];
__device__ int   g_cursor[Nn];
__device__ int   g_esrc[En];                      // src node of each CSR slot
__device__ int   g_bsum[64];
__device__ int   g_gbound[Bb + 1];
__device__ float g_hg[Bb * HD];

// ---------------- CSR build ------------------------------------------------
__global__ void k_zero_counts() {
    int i = blockIdx.x * blockDim.x + threadIdx.x;
    if (i < Nn) g_cursor[i] = 0;
}

__global__ void k_count(const int* __restrict__ dstv) {
    int e = blockIdx.x * blockDim.x + threadIdx.x;
    if (e < En) atomicAdd(&g_cursor[dstv[e]], 1);
}

// per-1024-chunk sums (49 blocks)
__global__ void k_bsum() {
    __shared__ int wsum[32];
    int t = threadIdx.x, b = blockIdx.x;
    int i = b * 1024 + t;
    int v = (i < Nn) ? g_cursor[i] : 0;
    #pragma unroll
    for (int off = 16; off; off >>= 1) v += __shfl_xor_sync(0xFFFFFFFFu, v, off);
    if ((t & 31) == 0) wsum[t >> 5] = v;
    __syncthreads();
    if (t < 32) {
        int s = wsum[t];
        #pragma unroll
        for (int off = 16; off; off >>= 1) s += __shfl_xor_sync(0xFFFFFFFFu, s, off);
        if (t == 0) g_bsum[b] = s;
    }
}

// parallel block-scan: carry from preceding block sums, local scan, write out
__global__ void k_scan2() {
    __shared__ int wsum[32];
    __shared__ int carry_s;
    int t = threadIdx.x, b = blockIdx.x;
    int lane = t & 31, wid = t >> 5;
    if (t < 32) {
        int c = (t < b) ? g_bsum[t] : 0;
        if (t + 32 < b) c += g_bsum[t + 32];
        #pragma unroll
        for (int off = 16; off; off >>= 1) c += __shfl_xor_sync(0xFFFFFFFFu, c, off);
        if (t == 0) carry_s = c;
    }
    int i = b * 1024 + t;
    int v = (i < Nn) ? g_cursor[i] : 0;
    int incl = v;
    #pragma unroll
    for (int off = 1; off < 32; off <<= 1) {
        int tv = __shfl_up_sync(0xFFFFFFFFu, incl, off);
        if (lane >= off) incl += tv;
    }
    if (lane == 31) wsum[wid] = incl;
    __syncthreads();
    if (wid == 0) {
        int s = wsum[lane];
        #pragma unroll
        for (int off = 1; off < 32; off <<= 1) {
            int tv = __shfl_up_sync(0xFFFFFFFFu, s, off);
            if (lane >= off) s += tv;
        }
        wsum[lane] = s;
    }
    __syncthreads();
    int woff = (wid > 0) ? wsum[wid - 1] : 0;
    int excl = carry_s + woff + incl - v;
    if (i < Nn) {
        g_rowoff[i] = excl;
        g_cursor[i] = excl;
    }
    if (b == 0 && t == 0) g_rowoff[Nn] = En;
}

__global__ void k_scatter(const int* __restrict__ srcv, const int* __restrict__ dstv) {
    int e = blockIdx.x * blockDim.x + threadIdx.x;
    if (e < En) {
        int p = atomicAdd(&g_cursor[dstv[e]], 1);
        g_esrc[p] = srcv[e];
    }
}

// ---------------- bf16 tensor-core GEMM (ldmatrix + m16n8k16) --------------
// ASEL=0: A is fp32 external (converted on load). ASEL=1: A is bf16 g_h1h.
__device__ __forceinline__ void mma_bf16(float* c, const uint32_t* a,
                                         uint32_t b0, uint32_t b1) {
    asm volatile(
        "mma.sync.aligned.m16n8k16.row.col.f32.bf16.bf16.f32 "
        "{%0,%1,%2,%3}, {%4,%5,%6,%7}, {%8,%9}, {%0,%1,%2,%3};"
        : "+f"(c[0]), "+f"(c[1]), "+f"(c[2]), "+f"(c[3])
        : "r"(a[0]), "r"(a[1]), "r"(a[2]), "r"(a[3]), "r"(b0), "r"(b1));
}

__device__ __forceinline__ void ldsm_x4(uint32_t* r, uint32_t addr) {
    asm volatile("ldmatrix.sync.aligned.m8n8.x4.shared.b16 {%0,%1,%2,%3}, [%4];"
                 : "=r"(r[0]), "=r"(r[1]), "=r"(r[2]), "=r"(r[3]) : "r"(addr));
}

__device__ __forceinline__ void ldsm_x2t(uint32_t& r0, uint32_t& r1, uint32_t addr) {
    asm volatile("ldmatrix.sync.aligned.m8n8.x2.trans.shared.b16 {%0,%1}, [%2];"
                 : "=r"(r0), "=r"(r1) : "r"(addr));
}

template <int ASEL>
__global__ __launch_bounds__(256, 2) void k_gemm_bf16(const float* __restrict__ Aext,
                                                      const float* __restrict__ W,
                                                      const float* __restrict__ al,
                                                      const float* __restrict__ ar,
                                                      int K) {
    __shared__ __nv_bfloat16 As[128][40];    // [m][k], stride 20 words: CF ldmatrix
    __shared__ __nv_bfloat16 Bs[32][136];    // [k][n], stride 68 words: CF ldmatrix
    int tid = threadIdx.x;
    int lane = tid & 31, wid = tid >> 5;
    int wm = wid & 3, wn = wid >> 2;          // 4 warps along M, 2 along N
    int row0 = blockIdx.y * 128, col0 = blockIdx.x * 128;
    int lr = lane >> 2, lc = lane & 3;

    uint32_t sA = (uint32_t)__cvta_generic_to_shared(&As[0][0]);
    uint32_t sB = (uint32_t)__cvta_generic_to_shared(&Bs[0][0]);

    float acc[2][8][4];
    #pragma unroll
    for (int mt = 0; mt < 2; mt++)
        #pragma unroll
        for (int nt = 0; nt < 8; nt++)
            #pragma unroll
            for (int j = 0; j < 4; j++) acc[mt][nt][j] = 0.f;

    uint32_t aAddrBase[2];
    #pragma unroll
    for (int mt = 0; mt < 2; mt++) {
        int m = wm * 32 + mt * 16 + (lane & 15);
        aAddrBase[mt] = sA + (uint32_t)(m * 80 + ((lane >> 4) << 4));
    }
    uint32_t bAddrBase = sB + (uint32_t)(((lane & 7) + ((lane >> 3) & 1) * 8) * 272);

    float4 paf[4];
    uint4  pau[2];
    float4 pb[4];

    if constexpr (ASEL == 0) {
        #pragma unroll
        for (int r = 0; r < 4; r++) {
            int idx = r * 256 + tid;
            int row = idx >> 3, c4 = (idx & 7) * 4;
            int gr = row0 + row;
            paf[r] = make_float4(0.f, 0.f, 0.f, 0.f);
            if (gr < Nn) paf[r] = *(const float4*)(Aext + (size_t)gr * K + c4);
        }
    } else {
        #pragma unroll
        for (int r = 0; r < 2; r++) {
            int idx = r * 256 + tid;
            int row = idx >> 2, c8 = (idx & 3) * 8;
            int gr = row0 + row;
            pau[r] = make_uint4(0u, 0u, 0u, 0u);
            if (gr < Nn) pau[r] = *(const uint4*)(g_h1h + (size_t)gr * K + c8);
        }
    }
    #pragma unroll
    for (int r = 0; r < 4; r++) {
        int idx = r * 256 + tid;
        int kr = idx >> 5, c4 = (idx & 31) * 4;
        pb[r] = *(const float4*)(W + (size_t)kr * HD + col0 + c4);
    }

    for (int k0 = 0; k0 < K; k0 += 32) {
        if constexpr (ASEL == 0) {
            #pragma unroll
            for (int r = 0; r < 4; r++) {
                int idx = r * 256 + tid;
                int row = idx >> 3, c4 = (idx & 7) * 4;
                __nv_bfloat162 p0 = __float22bfloat162_rn(make_float2(paf[r].x, paf[r].y));
                __nv_bfloat162 p1 = __float22bfloat162_rn(make_float2(paf[r].z, paf[r].w));
                uint2 u;
                u.x = *(uint32_t*)&p0; u.y = *(uint32_t*)&p1;
                *(uint2*)&As[row][c4] = u;
            }
        } else {
            #pragma unroll
            for (int r = 0; r < 2; r++) {
                int idx = r * 256 + tid;
                int row = idx >> 2, c8 = (idx & 3) * 8;
                *(uint4*)&As[row][c8] = pau[r];
            }
        }
        #pragma unroll
        for (int r = 0; r < 4; r++) {
            int idx = r * 256 + tid;
            int kr = idx >> 5, c4 = (idx & 31) * 4;
            __nv_bfloat162 p0 = __float22bfloat162_rn(make_float2(pb[r].x, pb[r].y));
            __nv_bfloat162 p1 = __float22bfloat162_rn(make_float2(pb[r].z, pb[r].w));
            uint2 u;
            u.x = *(uint32_t*)&p0; u.y = *(uint32_t*)&p1;
            *(uint2*)&Bs[kr][c4] = u;
        }
        __syncthreads();

        int kn = k0 + 32;
        if (kn < K) {
            if constexpr (ASEL == 0) {
                #pragma unroll
                for (int r = 0; r < 4; r++) {
                    int idx = r * 256 + tid;
                    int row = idx >> 3, c4 = (idx & 7) * 4;
                    int gr = row0 + row;
                    paf[r] = make_float4(0.f, 0.f, 0.f, 0.f);
                    if (gr < Nn) paf[r] = *(const float4*)(Aext + (size_t)gr * K + kn + c4);
                }
            } else {
                #pragma unroll
                for (int r = 0; r < 2; r++) {
                    int idx = r * 256 + tid;
                    int row = idx >> 2, c8 = (idx & 3) * 8;
                    int gr = row0 + row;
                    pau[r] = make_uint4(0u, 0u, 0u, 0u);
                    if (gr < Nn) pau[r] = *(const uint4*)(g_h1h + (size_t)gr * K + kn + c8);
                }
            }
            #pragma unroll
            for (int r = 0; r < 4; r++) {
                int idx = r * 256 + tid;
                int kr = idx >> 5, c4 = (idx & 31) * 4;
                pb[r] = *(const float4*)(W + (size_t)(kn + kr) * HD + col0 + c4);
            }
        }

        #pragma unroll
        for (int ks = 0; ks < 2; ks++) {
            uint32_t a[2][4];
            #pragma unroll
            for (int mt = 0; mt < 2; mt++)
                ldsm_x4(a[mt], aAddrBase[mt] + ks * 32);
            #pragma unroll
            for (int nt = 0; nt < 8; nt++) {
                int nb = wn * 64 + nt * 8;
                uint32_t b0, b1;
                ldsm_x2t(b0, b1, bAddrBase + (uint32_t)(ks * 16 * 272 + nb * 2));
                #pragma unroll
                for (int mt = 0; mt < 2; mt++)
                    mma_bf16(acc[mt][nt], a[mt], b0, b1);
            }
        }
        __syncthreads();
    }

    // ---- store z as bf16 ----
    #pragma unroll
    for (int mt = 0; mt < 2; mt++) {
        #pragma unroll
        for (int nt = 0; nt < 8; nt++) {
            int r = row0 + wm * 32 + mt * 16 + lr;
            int c = col0 + wn * 64 + nt * 8 + lc * 2;
            if (r < Nn)
                *(__nv_bfloat162*)&g_zh[(size_t)r * HD + c] =
                    __float22bfloat162_rn(make_float2(acc[mt][nt][0], acc[mt][nt][1]));
            if (r + 8 < Nn)
                *(__nv_bfloat162*)&g_zh[(size_t)(r + 8) * HD + c] =
                    __float22bfloat162_rn(make_float2(acc[mt][nt][2], acc[mt][nt][3]));
        }
    }

    // ---- fused el/er ----
    int head_base = (col0 >> 5) + wn * 2;
    float alc[2][8], arc[2][8];
    #pragma unroll
    for (int hs = 0; hs < 2; hs++)
        #pragma unroll
        for (int q = 0; q < 4; q++) {
            int d0 = q * 8 + lc * 2;
            int hg = head_base + hs;
            alc[hs][q * 2]     = al[hg * 32 + d0];
            alc[hs][q * 2 + 1] = al[hg * 32 + d0 + 1];
            arc[hs][q * 2]     = ar[hg * 32 + d0];
            arc[hs][q * 2 + 1] = ar[hg * 32 + d0 + 1];
        }
    float pel[4][2], per_[4][2];
    #pragma unroll
    for (int rs = 0; rs < 4; rs++)
        #pragma unroll
        for (int hs = 0; hs < 2; hs++) { pel[rs][hs] = 0.f; per_[rs][hs] = 0.f; }
    #pragma unroll
    for (int mt = 0; mt < 2; mt++)
        #pragma unroll
        for (int nt = 0; nt < 8; nt++) {
            int hs = nt >> 2, q = nt & 3;
            #pragma unroll
            for (int j = 0; j < 4; j++) {
                int rs = mt * 2 + (j >> 1);
                float a = acc[mt][nt][j];
                pel[rs][hs]  = fmaf(a, alc[hs][q * 2 + (j & 1)], pel[rs][hs]);
                per_[rs][hs] = fmaf(a, arc[hs][q * 2 + (j & 1)], per_[rs][hs]);
            }
        }
    #pragma unroll
    for (int rs = 0; rs < 4; rs++)
        #pragma unroll
        for (int hs = 0; hs < 2; hs++) {
            float v = pel[rs][hs], w = per_[rs][hs];
            v += __shfl_xor_sync(0xFFFFFFFFu, v, 1);
            v += __shfl_xor_sync(0xFFFFFFFFu, v, 2);
            w += __shfl_xor_sync(0xFFFFFFFFu, w, 1);
            w += __shfl_xor_sync(0xFFFFFFFFu, w, 2);
            if (lc == 0) {
                int r = row0 + wm * 32 + (rs >> 1) * 16 + (rs & 1) * 8 + lr;
                if (r < Nn) {
                    g_el[r * 8 + head_base + hs] = v;
                    g_er[r * 8 + head_base + hs] = w;
                }
            }
        }
}

// ------- warp-per-node aggregation: smem-staged weights, 2-edge unroll -----
// out_sel=1: write bf16 h1 (+relu). out_sel=0: write bf16 h2.
__global__ __launch_bounds__(256) void k_agg(const float* __restrict__ bias,
                                             int out_sel) {
    __shared__ float sw[8][32][8];
    int gw = (blockIdx.x * blockDim.x + threadIdx.x) >> 5;
    if (gw >= Nn) return;
    int lane = threadIdx.x & 31;
    int wloc = threadIdx.x >> 5;
    int s0 = g_rowoff[gw], s1 = g_rowoff[gw + 1];

    float acc[8];
    #pragma unroll
    for (int k = 0; k < 8; k++) acc[k] = 0.f;
    float smv = 0.f;

    if (s1 > s0) {
        float4 erA = *(const float4*)(g_er + (size_t)gw * 8);
        float4 erB = *(const float4*)(g_er + (size_t)gw * 8 + 4);
        float er8[8] = {erA.x, erA.y, erA.z, erA.w, erB.x, erB.y, erB.z, erB.w};

        for (int base = s0; base < s1; base += 32) {
            int idx = base + lane;
            int cnt = min(32, s1 - base);
            int sn_l = (idx < s1) ? g_esrc[idx] : 0;
            if (idx < s1) {
                float4 e0 = *(const float4*)(g_el + (size_t)sn_l * 8);
                float4 e1 = *(const float4*)(g_el + (size_t)sn_l * 8 + 4);
                float ev[8] = {e0.x + er8[0], e0.y + er8[1], e0.z + er8[2], e0.w + er8[3],
                               e1.x + er8[4], e1.y + er8[5], e1.z + er8[6], e1.w + er8[7]};
                float wv[8];
                #pragma unroll
                for (int k = 0; k < 8; k++) {
                    float t = ev[k] > 0.f ? ev[k] : SLOPE * ev[k];
                    wv[k] = __expf(t);
                }
                *(float4*)&sw[wloc][lane][0] = make_float4(wv[0], wv[1], wv[2], wv[3]);
                *(float4*)&sw[wloc][lane][4] = make_float4(wv[4], wv[5], wv[6], wv[7]);
            }
            __syncwarp();
            int hsel = lane >> 2;
            int j = 0;
            for (; j + 2 <= cnt; j += 2) {
                int sn0 = __shfl_sync(0xFFFFFFFFu, sn_l, j);
                int sn1 = __shfl_sync(0xFFFFFFFFu, sn_l, j + 1);
                float w0 = sw[wloc][j][hsel];
                float w1 = sw[wloc][j + 1][hsel];
                uint4 r0 = *(const uint4*)(g_zh + (size_t)sn0 * HD + lane * 8);
                uint4 r1 = *(const uint4*)(g_zh + (size_t)sn1 * HD + lane * 8);
                smv += w0 + w1;
                float2 a0 = __bfloat1622float2(*(__nv_bfloat162*)&r0.x);
                float2 a1 = __bfloat1622float2(*(__nv_bfloat162*)&r0.y);
                float2 a2 = __bfloat1622float2(*(__nv_bfloat162*)&r0.z);
                float2 a3 = __bfloat1622float2(*(__nv_bfloat162*)&r0.w);
                acc[0] = fmaf(w0, a0.x, acc[0]); acc[1] = fmaf(w0, a0.y, acc[1]);
                acc[2] = fmaf(w0, a1.x, acc[2]); acc[3] = fmaf(w0, a1.y, acc[3]);
                acc[4] = fmaf(w0, a2.x, acc[4]); acc[5] = fmaf(w0, a2.y, acc[5]);
                acc[6] = fmaf(w0, a3.x, acc[6]); acc[7] = fmaf(w0, a3.y, acc[7]);
                float2 b0 = __bfloat1622float2(*(__nv_bfloat162*)&r1.x);
                float2 b1 = __bfloat1622float2(*(__nv_bfloat162*)&r1.y);
                float2 b2 = __bfloat1622float2(*(__nv_bfloat162*)&r1.z);
                float2 b3 = __bfloat1622float2(*(__nv_bfloat162*)&r1.w);
                acc[0] = fmaf(w1, b0.x, acc[0]); acc[1] = fmaf(w1, b0.y, acc[1]);
                acc[2] = fmaf(w1, b1.x, acc[2]); acc[3] = fmaf(w1, b1.y, acc[3]);
                acc[4] = fmaf(w1, b2.x, acc[4]); acc[5] = fmaf(w1, b2.y, acc[5]);
                acc[6] = fmaf(w1, b3.x, acc[6]); acc[7] = fmaf(w1, b3.y, acc[7]);
            }
            if (j < cnt) {
                int sn = __shfl_sync(0xFFFFFFFFu, sn_l, j);
                float wv = sw[wloc][j][hsel];
                smv += wv;
                uint4 raw = *(const uint4*)(g_zh + (size_t)sn * HD + lane * 8);
                float2 f0 = __bfloat1622float2(*(__nv_bfloat162*)&raw.x);
                float2 f1 = __bfloat1622float2(*(__nv_bfloat162*)&raw.y);
                float2 f2 = __bfloat1622float2(*(__nv_bfloat162*)&raw.z);
                float2 f3 = __bfloat1622float2(*(__nv_bfloat162*)&raw.w);
                acc[0] = fmaf(wv, f0.x, acc[0]); acc[1] = fmaf(wv, f0.y, acc[1]);
                acc[2] = fmaf(wv, f1.x, acc[2]); acc[3] = fmaf(wv, f1.y, acc[3]);
                acc[4] = fmaf(wv, f2.x, acc[4]); acc[5] = fmaf(wv, f2.y, acc[5]);
                acc[6] = fmaf(wv, f3.x, acc[6]); acc[7] = fmaf(wv, f3.y, acc[7]);
            }
            __syncwarp();
        }
        float inv = __frcp_rn(smv);
        #pragma unroll
        for (int k = 0; k < 8; k++) acc[k] *= inv;
    }

    const float* bp = bias + lane * 8;
    float o[8];
    #pragma unroll
    for (int k = 0; k < 8; k++) o[k] = acc[k] + bp[k];

    if (out_sel) {
        #pragma unroll
        for (int k = 0; k < 8; k++) o[k] = fmaxf(o[k], 0.f);
    }
    __nv_bfloat16* dst = (out_sel ? g_h1h : g_h2h) + (size_t)gw * HD + lane * 8;
    __nv_bfloat162 q0 = __float22bfloat162_rn(make_float2(o[0], o[1]));
    __nv_bfloat162 q1 = __float22bfloat162_rn(make_float2(o[2], o[3]));
    __nv_bfloat162 q2 = __float22bfloat162_rn(make_float2(o[4], o[5]));
    __nv_bfloat162 q3 = __float22bfloat162_rn(make_float2(o[6], o[7]));
    uint4 u;
    u.x = *(uint32_t*)&q0; u.y = *(uint32_t*)&q1;
    u.z = *(uint32_t*)&q2; u.w = *(uint32_t*)&q3;
    *(uint4*)dst = u;
}

// ---------------- readout (R12-validated structure, bf16 h2) ---------------
__global__ void k_gbound_zero(const int* __restrict__ gid) {
    int t = blockIdx.x * blockDim.x + threadIdx.x;
    if (t < Bb * HD) g_hg[t] = 0.f;
    if (blockIdx.x == 0 && threadIdx.x <= Bb) {
        int g = threadIdx.x;
        int lo = 0, hi = Nn;
        while (lo < hi) {
            int mid = (lo + hi) >> 1;
            if (gid[mid] < g) lo = mid + 1;
            else hi = mid;
        }
        g_gbound[g] = lo;
    }
}

__global__ void k_mean_part() {  // grid=(Bb,8), block=HD
    int b = blockIdx.x, d = threadIdx.x;
    int s = g_gbound[b], e = g_gbound[b + 1];
    float sum = 0.f;
    for (int n = s + blockIdx.y; n < e; n += 8)
        sum += __bfloat162float(g_h2h[(size_t)n * HD + d]);
    atomicAdd(&g_hg[b * HD + d], sum);
}

__global__ void k_cls(const float* __restrict__ perm, const float* __restrict__ Wc,
                      const float* __restrict__ bc, float* __restrict__ out) {
    int t = blockIdx.x * blockDim.x + threadIdx.x;
    if (t >= Bb * Cc) return;
    int b = t / Cc, c = t % Cc;
    int cnt = g_gbound[b + 1] - g_gbound[b];
    float inv = 1.f / (float)(cnt > 0 ? cnt : 1);
    float sg = 0.f;
    #pragma unroll 4
    for (int i = 0; i < HD; i++) sg = fmaf(g_hg[b * HD + i], Wc[i * Cc + c], sg);
    float s = bc[c] + sg * inv;
    #pragma unroll 4
    for (int i = 0; i < PERMD; i++)
        s = fmaf(perm[b * PERMD + i], Wc[(HD + i) * Cc + c], s);
    out[t] = s;
}

// ---------------- launch: fork CSR chain onto a side stream ----------------
extern "C" void kernel_launch(void* const* d_in, const int* in_sizes, int n_in,
                              void* d_out, int out_size) {
    const float* h    = (const float*)d_in[0];
    const float* perm = (const float*)d_in[1];
    const float* W1   = (const float*)d_in[2];
    const float* al1  = (const float*)d_in[3];
    const float* ar1  = (const float*)d_in[4];
    const float* b1   = (const float*)d_in[5];
    const float* W2   = (const float*)d_in[6];
    const float* al2  = (const float*)d_in[7];
    const float* ar2  = (const float*)d_in[8];
    const float* b2   = (const float*)d_in[9];
    const float* Wc   = (const float*)d_in[10];
    const float* bc   = (const float*)d_in[11];
    const int*   src  = (const int*)d_in[12];
    const int*   dstv = (const int*)d_in[13];
    const int*   gid  = (const int*)d_in[14];
    float* out = (float*)d_out;

    cudaStream_t s0 = (cudaStream_t)0;       // capture-origin (legacy) stream
    cudaStream_t s2;
    cudaStreamCreateWithFlags(&s2, cudaStreamNonBlocking);
    cudaEvent_t eFork, eCsr, eGb;
    cudaEventCreateWithFlags(&eFork, cudaEventDisableTiming);
    cudaEventCreateWithFlags(&eCsr, cudaEventDisableTiming);
    cudaEventCreateWithFlags(&eGb, cudaEventDisableTiming);

    // fork side stream off the origin stream (capture-legal pattern)
    cudaEventRecord(eFork, s0);
    cudaStreamWaitEvent(s2, eFork, 0);

    // side stream: CSR build (needs only src/dst) + graph boundaries
    k_zero_counts<<<(Nn + 255) / 256, 256, 0, s2>>>();
    k_count<<<(En + 255) / 256, 256, 0, s2>>>(dstv);
    k_bsum<<<49, 1024, 0, s2>>>();
    k_scan2<<<49, 1024, 0, s2>>>();
    k_scatter<<<(En + 255) / 256, 256, 0, s2>>>(src, dstv);
    cudaEventRecord(eCsr, s2);
    k_gbound_zero<<<(Bb * HD + 255) / 256, 256, 0, s2>>>(gid);
    cudaEventRecord(eGb, s2);

    dim3 gemm_grid(HD / 128, (Nn + 127) / 128);
    int node_warp_blocks = (Nn * 32 + 255) / 256;

    // main stream: layer-1 GEMM overlaps CSR build
    k_gemm_bf16<0><<<gemm_grid, 256, 0, s0>>>(h, W1, al1, ar1, IN_DIM);
    cudaStreamWaitEvent(s0, eCsr, 0);        // join: agg needs rowoff/esrc
    k_agg<<<node_warp_blocks, 256, 0, s0>>>(b1, /*out=h1 bf16*/1);

    // layer 2 (A = bf16 g_h1h)
    k_gemm_bf16<1><<<gemm_grid, 256, 0, s0>>>(nullptr, W2, al2, ar2, HD);
    k_agg<<<node_warp_blocks, 256, 0, s0>>>(b2, /*out=h2 bf16*/0);

    // readout
    cudaStreamWaitEvent(s0, eGb, 0);         // join: mean needs g_hg/gbound
    k_mean_part<<<dim3(Bb, 8), HD, 0, s0>>>();
    k_cls<<<(Bb * Cc + 127) / 128, 128, 0, s0>>>(perm, Wc, bc, out);

    cudaEventDestroy(eFork);
    cudaEventDestroy(eCsr);
    cudaEventDestroy(eGb);
    cudaStreamDestroy(s2);
}

// round 16
// speedup vs baseline: 1.4556x; 1.0310x over previous
#include <cuda_runtime.h>
#include <cuda_bf16.h>
#include <math_constants.h>
#include <cstdint>

#define Nn 50000
#define En 500000
#define IN_DIM 128
#define Hh 8
#define HD 256
#define PERMD 100
#define Bb 64
#define Cc 10
#define SLOPE 0.2f

// ---------------- scratch (static device globals) --------------------------
__device__ __nv_bfloat16 g_zh[(size_t)Nn * HD];   // z (bf16) for edge gather
__device__ __nv_bfloat16 g_h1h[(size_t)Nn * HD];  // layer-1 output (bf16, relu'd)
__device__ __nv_bfloat16 g_h2h[(size_t)Nn * HD];  // layer-2 output (bf16, for mean)
__device__ __nv_bfloat16 g_w1h[IN_DIM * HD];      // W1 pre-converted bf16
__device__ __nv_bfloat16 g_w2h[HD * HD];          // W2 pre-converted bf16
__device__ float g_el[Nn * Hh];
__device__ float g_er[Nn * Hh];
__device__ int   g_rowoff[Nn + 1];
__device__ int   g_cursor[Nn];
__device__ int   g_esrc[En];                      // src node of each CSR slot
__device__ int   g_bsum[64];
__device__ int   g_gbound[Bb + 1];
__device__ float g_hg[Bb * HD];

// ---------------- weight pre-conversion (once) ------------------------------
__global__ void k_wconv(const float* __restrict__ W1, const float* __restrict__ W2) {
    int t = blockIdx.x * blockDim.x + threadIdx.x;
    if (t < IN_DIM * HD) g_w1h[t] = __float2bfloat16_rn(W1[t]);
    if (t < HD * HD)     g_w2h[t] = __float2bfloat16_rn(W2[t]);
}

// ---------------- CSR build ------------------------------------------------
__global__ void k_zero_counts() {
    int i = blockIdx.x * blockDim.x + threadIdx.x;
    if (i < Nn) g_cursor[i] = 0;
}

__global__ void k_count(const int* __restrict__ dstv) {
    int e = blockIdx.x * blockDim.x + threadIdx.x;
    if (e < En) atomicAdd(&g_cursor[dstv[e]], 1);
}

// per-1024-chunk sums (49 blocks)
__global__ void k_bsum() {
    __shared__ int wsum[32];
    int t = threadIdx.x, b = blockIdx.x;
    int i = b * 1024 + t;
    int v = (i < Nn) ? g_cursor[i] : 0;
    #pragma unroll
    for (int off = 16; off; off >>= 1) v += __shfl_xor_sync(0xFFFFFFFFu, v, off);
    if ((t & 31) == 0) wsum[t >> 5] = v;
    __syncthreads();
    if (t < 32) {
        int s = wsum[t];
        #pragma unroll
        for (int off = 16; off; off >>= 1) s += __shfl_xor_sync(0xFFFFFFFFu, s, off);
        if (t == 0) g_bsum[b] = s;
    }
}

// parallel block-scan: carry from preceding block sums, local scan, write out
__global__ void k_scan2() {
    __shared__ int wsum[32];
    __shared__ int carry_s;
    int t = threadIdx.x, b = blockIdx.x;
    int lane = t & 31, wid = t >> 5;
    if (t < 32) {
        int c = (t < b) ? g_bsum[t] : 0;
        if (t + 32 < b) c += g_bsum[t + 32];
        #pragma unroll
        for (int off = 16; off; off >>= 1) c += __shfl_xor_sync(0xFFFFFFFFu, c, off);
        if (t == 0) carry_s = c;
    }
    int i = b * 1024 + t;
    int v = (i < Nn) ? g_cursor[i] : 0;
    int incl = v;
    #pragma unroll
    for (int off = 1; off < 32; off <<= 1) {
        int tv = __shfl_up_sync(0xFFFFFFFFu, incl, off);
        if (lane >= off) incl += tv;
    }
    if (lane == 31) wsum[wid] = incl;
    __syncthreads();
    if (wid == 0) {
        int s = wsum[lane];
        #pragma unroll
        for (int off = 1; off < 32; off <<= 1) {
            int tv = __shfl_up_sync(0xFFFFFFFFu, s, off);
            if (lane >= off) s += tv;
        }
        wsum[lane] = s;
    }
    __syncthreads();
    int woff = (wid > 0) ? wsum[wid - 1] : 0;
    int excl = carry_s + woff + incl - v;
    if (i < Nn) {
        g_rowoff[i] = excl;
        g_cursor[i] = excl;
    }
    if (b == 0 && t == 0) g_rowoff[Nn] = En;
}

__global__ void k_scatter(const int* __restrict__ srcv, const int* __restrict__ dstv) {
    int e = blockIdx.x * blockDim.x + threadIdx.x;
    if (e < En) {
        int p = atomicAdd(&g_cursor[dstv[e]], 1);
        g_esrc[p] = srcv[e];
    }
}

// ---------------- bf16 tensor-core GEMM (ldmatrix + m16n8k16) --------------
// ASEL=0: A = fp32 Aext (cvt on load), W = g_w1h. ASEL=1: A = g_h1h, W = g_w2h.
__device__ __forceinline__ void mma_bf16(float* c, const uint32_t* a,
                                         uint32_t b0, uint32_t b1) {
    asm volatile(
        "mma.sync.aligned.m16n8k16.row.col.f32.bf16.bf16.f32 "
        "{%0,%1,%2,%3}, {%4,%5,%6,%7}, {%8,%9}, {%0,%1,%2,%3};"
        : "+f"(c[0]), "+f"(c[1]), "+f"(c[2]), "+f"(c[3])
        : "r"(a[0]), "r"(a[1]), "r"(a[2]), "r"(a[3]), "r"(b0), "r"(b1));
}

__device__ __forceinline__ void ldsm_x4(uint32_t* r, uint32_t addr) {
    asm volatile("ldmatrix.sync.aligned.m8n8.x4.shared.b16 {%0,%1,%2,%3}, [%4];"
                 : "=r"(r[0]), "=r"(r[1]), "=r"(r[2]), "=r"(r[3]) : "r"(addr));
}

__device__ __forceinline__ void ldsm_x2t(uint32_t& r0, uint32_t& r1, uint32_t addr) {
    asm volatile("ldmatrix.sync.aligned.m8n8.x2.trans.shared.b16 {%0,%1}, [%2];"
                 : "=r"(r0), "=r"(r1) : "r"(addr));
}

template <int ASEL>
__global__ __launch_bounds__(256, 2) void k_gemm_bf16(const float* __restrict__ Aext,
                                                      const float* __restrict__ al,
                                                      const float* __restrict__ ar,
                                                      int K) {
    const __nv_bfloat16* Wh = ASEL ? g_w2h : g_w1h;   // device-side symbol ref
    __shared__ __nv_bfloat16 As[128][40];    // [m][k], stride 20 words: CF ldmatrix
    __shared__ __nv_bfloat16 Bs[32][136];    // [k][n], stride 68 words: CF ldmatrix
    int tid = threadIdx.x;
    int lane = tid & 31, wid = tid >> 5;
    int wm = wid & 3, wn = wid >> 2;          // 4 warps along M, 2 along N
    int row0 = blockIdx.y * 128, col0 = blockIdx.x * 128;
    int lr = lane >> 2, lc = lane & 3;

    uint32_t sA = (uint32_t)__cvta_generic_to_shared(&As[0][0]);
    uint32_t sB = (uint32_t)__cvta_generic_to_shared(&Bs[0][0]);

    float acc[2][8][4];
    #pragma unroll
    for (int mt = 0; mt < 2; mt++)
        #pragma unroll
        for (int nt = 0; nt < 8; nt++)
            #pragma unroll
            for (int j = 0; j < 4; j++) acc[mt][nt][j] = 0.f;

    uint32_t aAddrBase[2];
    #pragma unroll
    for (int mt = 0; mt < 2; mt++) {
        int m = wm * 32 + mt * 16 + (lane & 15);
        aAddrBase[mt] = sA + (uint32_t)(m * 80 + ((lane >> 4) << 4));
    }
    uint32_t bAddrBase = sB + (uint32_t)(((lane & 7) + ((lane >> 3) & 1) * 8) * 272);

    float4 paf[4];
    uint4  pau[2];
    uint4  pbu[2];

    if constexpr (ASEL == 0) {
        #pragma unroll
        for (int r = 0; r < 4; r++) {
            int idx = r * 256 + tid;
            int row = idx >> 3, c4 = (idx & 7) * 4;
            int gr = row0 + row;
            paf[r] = make_float4(0.f, 0.f, 0.f, 0.f);
            if (gr < Nn) paf[r] = *(const float4*)(Aext + (size_t)gr * K + c4);
        }
    } else {
        #pragma unroll
        for (int r = 0; r < 2; r++) {
            int idx = r * 256 + tid;
            int row = idx >> 2, c8 = (idx & 3) * 8;
            int gr = row0 + row;
            pau[r] = make_uint4(0u, 0u, 0u, 0u);
            if (gr < Nn) pau[r] = *(const uint4*)(g_h1h + (size_t)gr * K + c8);
        }
    }
    #pragma unroll
    for (int r = 0; r < 2; r++) {
        int idx = r * 256 + tid;
        int kr = idx >> 4, c8 = (idx & 15) * 8;
        pbu[r] = *(const uint4*)(Wh + (size_t)kr * HD + col0 + c8);
    }

    for (int k0 = 0; k0 < K; k0 += 32) {
        // deposit prefetched A tile
        if constexpr (ASEL == 0) {
            #pragma unroll
            for (int r = 0; r < 4; r++) {
                int idx = r * 256 + tid;
                int row = idx >> 3, c4 = (idx & 7) * 4;
                __nv_bfloat162 p0 = __float22bfloat162_rn(make_float2(paf[r].x, paf[r].y));
                __nv_bfloat162 p1 = __float22bfloat162_rn(make_float2(paf[r].z, paf[r].w));
                uint2 u;
                u.x = *(uint32_t*)&p0; u.y = *(uint32_t*)&p1;
                *(uint2*)&As[row][c4] = u;
            }
        } else {
            #pragma unroll
            for (int r = 0; r < 2; r++) {
                int idx = r * 256 + tid;
                int row = idx >> 2, c8 = (idx & 3) * 8;
                *(uint4*)&As[row][c8] = pau[r];
            }
        }
        // deposit prefetched B tile (already bf16)
        #pragma unroll
        for (int r = 0; r < 2; r++) {
            int idx = r * 256 + tid;
            int kr = idx >> 4, c8 = (idx & 15) * 8;
            *(uint4*)&Bs[kr][c8] = pbu[r];
        }
        __syncthreads();

        // issue next-tile loads BEFORE compute (overlap global latency w/ MMA)
        int kn = k0 + 32;
        if (kn < K) {
            if constexpr (ASEL == 0) {
                #pragma unroll
                for (int r = 0; r < 4; r++) {
                    int idx = r * 256 + tid;
                    int row = idx >> 3, c4 = (idx & 7) * 4;
                    int gr = row0 + row;
                    paf[r] = make_float4(0.f, 0.f, 0.f, 0.f);
                    if (gr < Nn) paf[r] = *(const float4*)(Aext + (size_t)gr * K + kn + c4);
                }
            } else {
                #pragma unroll
                for (int r = 0; r < 2; r++) {
                    int idx = r * 256 + tid;
                    int row = idx >> 2, c8 = (idx & 3) * 8;
                    int gr = row0 + row;
                    pau[r] = make_uint4(0u, 0u, 0u, 0u);
                    if (gr < Nn) pau[r] = *(const uint4*)(g_h1h + (size_t)gr * K + kn + c8);
                }
            }
            #pragma unroll
            for (int r = 0; r < 2; r++) {
                int idx = r * 256 + tid;
                int kr = idx >> 4, c8 = (idx & 15) * 8;
                pbu[r] = *(const uint4*)(Wh + (size_t)(kn + kr) * HD + col0 + c8);
            }
        }

        #pragma unroll
        for (int ks = 0; ks < 2; ks++) {
            uint32_t a[2][4];
            #pragma unroll
            for (int mt = 0; mt < 2; mt++)
                ldsm_x4(a[mt], aAddrBase[mt] + ks * 32);
            #pragma unroll
            for (int nt = 0; nt < 8; nt++) {
                int nb = wn * 64 + nt * 8;
                uint32_t b0, b1;
                ldsm_x2t(b0, b1, bAddrBase + (uint32_t)(ks * 16 * 272 + nb * 2));
                #pragma unroll
                for (int mt = 0; mt < 2; mt++)
                    mma_bf16(acc[mt][nt], a[mt], b0, b1);
            }
        }
        __syncthreads();
    }

    // ---- store z as bf16 ----
    #pragma unroll
    for (int mt = 0; mt < 2; mt++) {
        #pragma unroll
        for (int nt = 0; nt < 8; nt++) {
            int r = row0 + wm * 32 + mt * 16 + lr;
            int c = col0 + wn * 64 + nt * 8 + lc * 2;
            if (r < Nn)
                *(__nv_bfloat162*)&g_zh[(size_t)r * HD + c] =
                    __float22bfloat162_rn(make_float2(acc[mt][nt][0], acc[mt][nt][1]));
            if (r + 8 < Nn)
                *(__nv_bfloat162*)&g_zh[(size_t)(r + 8) * HD + c] =
                    __float22bfloat162_rn(make_float2(acc[mt][nt][2], acc[mt][nt][3]));
        }
    }

    // ---- fused el/er ----
    int head_base = (col0 >> 5) + wn * 2;
    float alc[2][8], arc[2][8];
    #pragma unroll
    for (int hs = 0; hs < 2; hs++)
        #pragma unroll
        for (int q = 0; q < 4; q++) {
            int d0 = q * 8 + lc * 2;
            int hg = head_base + hs;
            alc[hs][q * 2]     = al[hg * 32 + d0];
            alc[hs][q * 2 + 1] = al[hg * 32 + d0 + 1];
            arc[hs][q * 2]     = ar[hg * 32 + d0];
            arc[hs][q * 2 + 1] = ar[hg * 32 + d0 + 1];
        }
    float pel[4][2], per_[4][2];
    #pragma unroll
    for (int rs = 0; rs < 4; rs++)
        #pragma unroll
        for (int hs = 0; hs < 2; hs++) { pel[rs][hs] = 0.f; per_[rs][hs] = 0.f; }
    #pragma unroll
    for (int mt = 0; mt < 2; mt++)
        #pragma unroll
        for (int nt = 0; nt < 8; nt++) {
            int hs = nt >> 2, q = nt & 3;
            #pragma unroll
            for (int j = 0; j < 4; j++) {
                int rs = mt * 2 + (j >> 1);
                float a = acc[mt][nt][j];
                pel[rs][hs]  = fmaf(a, alc[hs][q * 2 + (j & 1)], pel[rs][hs]);
                per_[rs][hs] = fmaf(a, arc[hs][q * 2 + (j & 1)], per_[rs][hs]);
            }
        }
    #pragma unroll
    for (int rs = 0; rs < 4; rs++)
        #pragma unroll
        for (int hs = 0; hs < 2; hs++) {
            float v = pel[rs][hs], w = per_[rs][hs];
            v += __shfl_xor_sync(0xFFFFFFFFu, v, 1);
            v += __shfl_xor_sync(0xFFFFFFFFu, v, 2);
            w += __shfl_xor_sync(0xFFFFFFFFu, w, 1);
            w += __shfl_xor_sync(0xFFFFFFFFu, w, 2);
            if (lc == 0) {
                int r = row0 + wm * 32 + (rs >> 1) * 16 + (rs & 1) * 8 + lr;
                if (r < Nn) {
                    g_el[r * 8 + head_base + hs] = v;
                    g_er[r * 8 + head_base + hs] = w;
                }
            }
        }
}

// ------- warp-per-node aggregation: smem-staged weights, 2-edge unroll -----
// out_sel=1: write bf16 h1 (+relu). out_sel=0: write bf16 h2.
__global__ __launch_bounds__(256) void k_agg(const float* __restrict__ bias,
                                             int out_sel) {
    __shared__ float sw[8][32][8];
    int gw = (blockIdx.x * blockDim.x + threadIdx.x) >> 5;
    if (gw >= Nn) return;
    int lane = threadIdx.x & 31;
    int wloc = threadIdx.x >> 5;
    int s0 = g_rowoff[gw], s1 = g_rowoff[gw + 1];

    float acc[8];
    #pragma unroll
    for (int k = 0; k < 8; k++) acc[k] = 0.f;
    float smv = 0.f;

    if (s1 > s0) {
        float4 erA = *(const float4*)(g_er + (size_t)gw * 8);
        float4 erB = *(const float4*)(g_er + (size_t)gw * 8 + 4);
        float er8[8] = {erA.x, erA.y, erA.z, erA.w, erB.x, erB.y, erB.z, erB.w};

        for (int base = s0; base < s1; base += 32) {
            int idx = base + lane;
            int cnt = min(32, s1 - base);
            int sn_l = (idx < s1) ? g_esrc[idx] : 0;
            if (idx < s1) {
                float4 e0 = *(const float4*)(g_el + (size_t)sn_l * 8);
                float4 e1 = *(const float4*)(g_el + (size_t)sn_l * 8 + 4);
                float ev[8] = {e0.x + er8[0], e0.y + er8[1], e0.z + er8[2], e0.w + er8[3],
                               e1.x + er8[4], e1.y + er8[5], e1.z + er8[6], e1.w + er8[7]};
                float wv[8];
                #pragma unroll
                for (int k = 0; k < 8; k++) {
                    float t = ev[k] > 0.f ? ev[k] : SLOPE * ev[k];
                    wv[k] = __expf(t);
                }
                *(float4*)&sw[wloc][lane][0] = make_float4(wv[0], wv[1], wv[2], wv[3]);
                *(float4*)&sw[wloc][lane][4] = make_float4(wv[4], wv[5], wv[6], wv[7]);
            }
            __syncwarp();
            int hsel = lane >> 2;
            int j = 0;
            for (; j + 2 <= cnt; j += 2) {
                int sn0 = __shfl_sync(0xFFFFFFFFu, sn_l, j);
                int sn1 = __shfl_sync(0xFFFFFFFFu, sn_l, j + 1);
                float w0 = sw[wloc][j][hsel];
                float w1 = sw[wloc][j + 1][hsel];
                uint4 r0 = *(const uint4*)(g_zh + (size_t)sn0 * HD + lane * 8);
                uint4 r1 = *(const uint4*)(g_zh + (size_t)sn1 * HD + lane * 8);
                smv += w0 + w1;
                float2 a0 = __bfloat1622float2(*(__nv_bfloat162*)&r0.x);
                float2 a1 = __bfloat1622float2(*(__nv_bfloat162*)&r0.y);
                float2 a2 = __bfloat1622float2(*(__nv_bfloat162*)&r0.z);
                float2 a3 = __bfloat1622float2(*(__nv_bfloat162*)&r0.w);
                acc[0] = fmaf(w0, a0.x, acc[0]); acc[1] = fmaf(w0, a0.y, acc[1]);
                acc[2] = fmaf(w0, a1.x, acc[2]); acc[3] = fmaf(w0, a1.y, acc[3]);
                acc[4] = fmaf(w0, a2.x, acc[4]); acc[5] = fmaf(w0, a2.y, acc[5]);
                acc[6] = fmaf(w0, a3.x, acc[6]); acc[7] = fmaf(w0, a3.y, acc[7]);
                float2 b0 = __bfloat1622float2(*(__nv_bfloat162*)&r1.x);
                float2 b1 = __bfloat1622float2(*(__nv_bfloat162*)&r1.y);
                float2 b2 = __bfloat1622float2(*(__nv_bfloat162*)&r1.z);
                float2 b3 = __bfloat1622float2(*(__nv_bfloat162*)&r1.w);
                acc[0] = fmaf(w1, b0.x, acc[0]); acc[1] = fmaf(w1, b0.y, acc[1]);
                acc[2] = fmaf(w1, b1.x, acc[2]); acc[3] = fmaf(w1, b1.y, acc[3]);
                acc[4] = fmaf(w1, b2.x, acc[4]); acc[5] = fmaf(w1, b2.y, acc[5]);
                acc[6] = fmaf(w1, b3.x, acc[6]); acc[7] = fmaf(w1, b3.y, acc[7]);
            }
            if (j < cnt) {
                int sn = __shfl_sync(0xFFFFFFFFu, sn_l, j);
                float wv = sw[wloc][j][hsel];
                smv += wv;
                uint4 raw = *(const uint4*)(g_zh + (size_t)sn * HD + lane * 8);
                float2 f0 = __bfloat1622float2(*(__nv_bfloat162*)&raw.x);
                float2 f1 = __bfloat1622float2(*(__nv_bfloat162*)&raw.y);
                float2 f2 = __bfloat1622float2(*(__nv_bfloat162*)&raw.z);
                float2 f3 = __bfloat1622float2(*(__nv_bfloat162*)&raw.w);
                acc[0] = fmaf(wv, f0.x, acc[0]); acc[1] = fmaf(wv, f0.y, acc[1]);
                acc[2] = fmaf(wv, f1.x, acc[2]); acc[3] = fmaf(wv, f1.y, acc[3]);
                acc[4] = fmaf(wv, f2.x, acc[4]); acc[5] = fmaf(wv, f2.y, acc[5]);
                acc[6] = fmaf(wv, f3.x, acc[6]); acc[7] = fmaf(wv, f3.y, acc[7]);
            }
            __syncwarp();
        }
        float inv = __frcp_rn(smv);
        #pragma unroll
        for (int k = 0; k < 8; k++) acc[k] *= inv;
    }

    const float* bp = bias + lane * 8;
    float o[8];
    #pragma unroll
    for (int k = 0; k < 8; k++) o[k] = acc[k] + bp[k];

    if (out_sel) {
        #pragma unroll
        for (int k = 0; k < 8; k++) o[k] = fmaxf(o[k], 0.f);
    }
    __nv_bfloat16* dst = (out_sel ? g_h1h : g_h2h) + (size_t)gw * HD + lane * 8;
    __nv_bfloat162 q0 = __float22bfloat162_rn(make_float2(o[0], o[1]));
    __nv_bfloat162 q1 = __float22bfloat162_rn(make_float2(o[2], o[3]));
    __nv_bfloat162 q2 = __float22bfloat162_rn(make_float2(o[4], o[5]));
    __nv_bfloat162 q3 = __float22bfloat162_rn(make_float2(o[6], o[7]));
    uint4 u;
    u.x = *(uint32_t*)&q0; u.y = *(uint32_t*)&q1;
    u.z = *(uint32_t*)&q2; u.w = *(uint32_t*)&q3;
    *(uint4*)dst = u;
}

// ---------------- readout --------------------------------------------------
__global__ void k_gbound_zero(const int* __restrict__ gid) {
    int t = blockIdx.x * blockDim.x + threadIdx.x;
    if (t < Bb * HD) g_hg[t] = 0.f;
    if (blockIdx.x == 0 && threadIdx.x <= Bb) {
        int g = threadIdx.x;
        int lo = 0, hi = Nn;
        while (lo < hi) {
            int mid = (lo + hi) >> 1;
            if (gid[mid] < g) lo = mid + 1;
            else hi = mid;
        }
        g_gbound[g] = lo;
    }
}

__global__ void k_mean_part() {  // grid=(Bb,8), block=HD
    int b = blockIdx.x, d = threadIdx.x;
    int s = g_gbound[b], e = g_gbound[b + 1];
    float sum = 0.f;
    for (int n = s + blockIdx.y; n < e; n += 8)
        sum += __bfloat162float(g_h2h[(size_t)n * HD + d]);
    atomicAdd(&g_hg[b * HD + d], sum);
}

__global__ void k_cls(const float* __restrict__ perm, const float* __restrict__ Wc,
                      const float* __restrict__ bc, float* __restrict__ out) {
    int t = blockIdx.x * blockDim.x + threadIdx.x;
    if (t >= Bb * Cc) return;
    int b = t / Cc, c = t % Cc;
    int cnt = g_gbound[b + 1] - g_gbound[b];
    float inv = 1.f / (float)(cnt > 0 ? cnt : 1);
    float sg = 0.f;
    #pragma unroll 4
    for (int i = 0; i < HD; i++) sg = fmaf(g_hg[b * HD + i], Wc[i * Cc + c], sg);
    float s = bc[c] + sg * inv;
    #pragma unroll 4
    for (int i = 0; i < PERMD; i++)
        s = fmaf(perm[b * PERMD + i], Wc[(HD + i) * Cc + c], s);
    out[t] = s;
}

// ---------------- launch: fork CSR chain onto a side stream ----------------
extern "C" void kernel_launch(void* const* d_in, const int* in_sizes, int n_in,
                              void* d_out, int out_size) {
    const float* h    = (const float*)d_in[0];
    const float* perm = (const float*)d_in[1];
    const float* W1   = (const float*)d_in[2];
    const float* al1  = (const float*)d_in[3];
    const float* ar1  = (const float*)d_in[4];
    const float* b1   = (const float*)d_in[5];
    const float* W2   = (const float*)d_in[6];
    const float* al2  = (const float*)d_in[7];
    const float* ar2  = (const float*)d_in[8];
    const float* b2   = (const float*)d_in[9];
    const float* Wc   = (const float*)d_in[10];
    const float* bc   = (const float*)d_in[11];
    const int*   src  = (const int*)d_in[12];
    const int*   dstv = (const int*)d_in[13];
    const int*   gid  = (const int*)d_in[14];
    float* out = (float*)d_out;

    cudaStream_t s0 = (cudaStream_t)0;       // capture-origin (legacy) stream
    cudaStream_t s2;
    cudaStreamCreateWithFlags(&s2, cudaStreamNonBlocking);
    cudaEvent_t eFork, eCsr, eGb;
    cudaEventCreateWithFlags(&eFork, cudaEventDisableTiming);
    cudaEventCreateWithFlags(&eCsr, cudaEventDisableTiming);
    cudaEventCreateWithFlags(&eGb, cudaEventDisableTiming);

    // fork side stream off the origin stream (capture-legal pattern)
    cudaEventRecord(eFork, s0);
    cudaStreamWaitEvent(s2, eFork, 0);

    // side stream: CSR build (needs only src/dst) + graph boundaries
    k_zero_counts<<<(Nn + 255) / 256, 256, 0, s2>>>();
    k_count<<<(En + 255) / 256, 256, 0, s2>>>(dstv);
    k_bsum<<<49, 1024, 0, s2>>>();
    k_scan2<<<49, 1024, 0, s2>>>();
    k_scatter<<<(En + 255) / 256, 256, 0, s2>>>(src, dstv);
    cudaEventRecord(eCsr, s2);
    k_gbound_zero<<<(Bb * HD + 255) / 256, 256, 0, s2>>>(gid);
    cudaEventRecord(eGb, s2);

    dim3 gemm_grid(HD / 128, (Nn + 127) / 128);
    int node_warp_blocks = (Nn * 32 + 255) / 256;

    // main stream: weight pre-conversion (once), then layer-1 GEMM overlapping CSR
    k_wconv<<<(HD * HD + 255) / 256, 256, 0, s0>>>(W1, W2);
    k_gemm_bf16<0><<<gemm_grid, 256, 0, s0>>>(h, al1, ar1, IN_DIM);
    cudaStreamWaitEvent(s0, eCsr, 0);        // join: agg needs rowoff/esrc
    k_agg<<<node_warp_blocks, 256, 0, s0>>>(b1, /*out=h1 bf16*/1);

    // layer 2 (A = bf16 g_h1h, W = bf16 g_w2h — selected inside kernel)
    k_gemm_bf16<1><<<gemm_grid, 256, 0, s0>>>(nullptr, al2, ar2, HD);
    k_agg<<<node_warp_blocks, 256, 0, s0>>>(b2, /*out=h2 bf16*/0);

    // readout
    cudaStreamWaitEvent(s0, eGb, 0);         // join: mean needs g_hg/gbound
    k_mean_part<<<dim3(Bb, 8), HD, 0, s0>>>();
    k_cls<<<(Bb * Cc + 127) / 128, 128, 0, s0>>>(perm, Wc, bc, out);

    cudaEventDestroy(eFork);
    cudaEventDestroy(eCsr);
    cudaEventDestroy(eGb);
    cudaStreamDestroy(s2);
}

// round 17
// speedup vs baseline: 1.5391x; 1.0574x over previous
#include <cuda_runtime.h>
#include <cuda_bf16.h>
#include <math_constants.h>
#include <cstdint>

#define Nn 50000
#define En 500000
#define IN_DIM 128
#define Hh 8
#define HD 256
#define PERMD 100
#define Bb 64
#define Cc 10
#define SLOPE 0.2f

// ---------------- scratch (static device globals) --------------------------
__device__ __nv_bfloat16 g_zh[(size_t)Nn * HD];   // z (bf16) for edge gather
__device__ __nv_bfloat16 g_h1h[(size_t)Nn * HD];  // layer-1 output (bf16, relu'd)
__device__ __nv_bfloat16 g_h2h[(size_t)Nn * HD];  // layer-2 output (bf16, for mean)
__device__ __nv_bfloat16 g_w1h[IN_DIM * HD];      // W1 pre-converted bf16
__device__ __nv_bfloat16 g_w2h[HD * HD];          // W2 pre-converted bf16
__device__ float g_el[Nn * Hh];
__device__ float g_er[Nn * Hh];
__device__ int   g_rowoff[Nn + 1];
__device__ int   g_cursor[Nn];
__device__ int   g_esrc[En];                      // src node of each CSR slot
__device__ int   g_bsum[64];
__device__ int   g_gbound[Bb + 1];
__device__ float g_hg[Bb * HD];

// ---------------- weight pre-conversion (once) ------------------------------
__global__ void k_wconv(const float* __restrict__ W1, const float* __restrict__ W2) {
    int t = blockIdx.x * blockDim.x + threadIdx.x;
    if (t < IN_DIM * HD) g_w1h[t] = __float2bfloat16_rn(W1[t]);
    if (t < HD * HD)     g_w2h[t] = __float2bfloat16_rn(W2[t]);
}

// ---------------- CSR build ------------------------------------------------
__global__ void k_zero_counts() {
    int i = blockIdx.x * blockDim.x + threadIdx.x;
    if (i < Nn) g_cursor[i] = 0;
}

__global__ void k_count(const int* __restrict__ dstv) {
    int e = blockIdx.x * blockDim.x + threadIdx.x;
    if (e < En) atomicAdd(&g_cursor[dstv[e]], 1);
}

// per-1024-chunk sums (49 blocks)
__global__ void k_bsum() {
    __shared__ int wsum[32];
    int t = threadIdx.x, b = blockIdx.x;
    int i = b * 1024 + t;
    int v = (i < Nn) ? g_cursor[i] : 0;
    #pragma unroll
    for (int off = 16; off; off >>= 1) v += __shfl_xor_sync(0xFFFFFFFFu, v, off);
    if ((t & 31) == 0) wsum[t >> 5] = v;
    __syncthreads();
    if (t < 32) {
        int s = wsum[t];
        #pragma unroll
        for (int off = 16; off; off >>= 1) s += __shfl_xor_sync(0xFFFFFFFFu, s, off);
        if (t == 0) g_bsum[b] = s;
    }
}

// parallel block-scan: carry from preceding block sums, local scan, write out
__global__ void k_scan2() {
    __shared__ int wsum[32];
    __shared__ int carry_s;
    int t = threadIdx.x, b = blockIdx.x;
    int lane = t & 31, wid = t >> 5;
    if (t < 32) {
        int c = (t < b) ? g_bsum[t] : 0;
        if (t + 32 < b) c += g_bsum[t + 32];
        #pragma unroll
        for (int off = 16; off; off >>= 1) c += __shfl_xor_sync(0xFFFFFFFFu, c, off);
        if (t == 0) carry_s = c;
    }
    int i = b * 1024 + t;
    int v = (i < Nn) ? g_cursor[i] : 0;
    int incl = v;
    #pragma unroll
    for (int off = 1; off < 32; off <<= 1) {
        int tv = __shfl_up_sync(0xFFFFFFFFu, incl, off);
        if (lane >= off) incl += tv;
    }
    if (lane == 31) wsum[wid] = incl;
    __syncthreads();
    if (wid == 0) {
        int s = wsum[lane];
        #pragma unroll
        for (int off = 1; off < 32; off <<= 1) {
            int tv = __shfl_up_sync(0xFFFFFFFFu, s, off);
            if (lane >= off) s += tv;
        }
        wsum[lane] = s;
    }
    __syncthreads();
    int woff = (wid > 0) ? wsum[wid - 1] : 0;
    int excl = carry_s + woff + incl - v;
    if (i < Nn) {
        g_rowoff[i] = excl;
        g_cursor[i] = excl;
    }
    if (b == 0 && t == 0) g_rowoff[Nn] = En;
}

__global__ void k_scatter(const int* __restrict__ srcv, const int* __restrict__ dstv) {
    int e = blockIdx.x * blockDim.x + threadIdx.x;
    if (e < En) {
        int p = atomicAdd(&g_cursor[dstv[e]], 1);
        g_esrc[p] = srcv[e];
    }
}

// ---------------- bf16 tensor-core GEMM (ldmatrix + m16n8k16) --------------
// ASEL=0: A = fp32 Aext (cvt on load), W = g_w1h. ASEL=1: A = g_h1h, W = g_w2h.
__device__ __forceinline__ void mma_bf16(float* c, const uint32_t* a,
                                         uint32_t b0, uint32_t b1) {
    asm volatile(
        "mma.sync.aligned.m16n8k16.row.col.f32.bf16.bf16.f32 "
        "{%0,%1,%2,%3}, {%4,%5,%6,%7}, {%8,%9}, {%0,%1,%2,%3};"
        : "+f"(c[0]), "+f"(c[1]), "+f"(c[2]), "+f"(c[3])
        : "r"(a[0]), "r"(a[1]), "r"(a[2]), "r"(a[3]), "r"(b0), "r"(b1));
}

__device__ __forceinline__ void ldsm_x4(uint32_t* r, uint32_t addr) {
    asm volatile("ldmatrix.sync.aligned.m8n8.x4.shared.b16 {%0,%1,%2,%3}, [%4];"
                 : "=r"(r[0]), "=r"(r[1]), "=r"(r[2]), "=r"(r[3]) : "r"(addr));
}

__device__ __forceinline__ void ldsm_x2t(uint32_t& r0, uint32_t& r1, uint32_t addr) {
    asm volatile("ldmatrix.sync.aligned.m8n8.x2.trans.shared.b16 {%0,%1}, [%2];"
                 : "=r"(r0), "=r"(r1) : "r"(addr));
}

template <int ASEL>
__global__ __launch_bounds__(256, 2) void k_gemm_bf16(const float* __restrict__ Aext,
                                                      const float* __restrict__ al,
                                                      const float* __restrict__ ar,
                                                      int K) {
    const __nv_bfloat16* Wh = ASEL ? g_w2h : g_w1h;   // device-side symbol ref
    __shared__ __nv_bfloat16 As[128][40];    // [m][k], stride 20 words: CF ldmatrix
    __shared__ __nv_bfloat16 Bs[32][136];    // [k][n], stride 68 words: CF ldmatrix
    int tid = threadIdx.x;
    int lane = tid & 31, wid = tid >> 5;
    int wm = wid & 3, wn = wid >> 2;          // 4 warps along M, 2 along N
    int row0 = blockIdx.y * 128, col0 = blockIdx.x * 128;
    int lr = lane >> 2, lc = lane & 3;

    uint32_t sA = (uint32_t)__cvta_generic_to_shared(&As[0][0]);
    uint32_t sB = (uint32_t)__cvta_generic_to_shared(&Bs[0][0]);

    float acc[2][8][4];
    #pragma unroll
    for (int mt = 0; mt < 2; mt++)
        #pragma unroll
        for (int nt = 0; nt < 8; nt++)
            #pragma unroll
            for (int j = 0; j < 4; j++) acc[mt][nt][j] = 0.f;

    uint32_t aAddrBase[2];
    #pragma unroll
    for (int mt = 0; mt < 2; mt++) {
        int m = wm * 32 + mt * 16 + (lane & 15);
        aAddrBase[mt] = sA + (uint32_t)(m * 80 + ((lane >> 4) << 4));
    }
    uint32_t bAddrBase = sB + (uint32_t)(((lane & 7) + ((lane >> 3) & 1) * 8) * 272);

    float4 paf[4];
    uint4  pau[2];
    uint4  pbu[2];

    if constexpr (ASEL == 0) {
        #pragma unroll
        for (int r = 0; r < 4; r++) {
            int idx = r * 256 + tid;
            int row = idx >> 3, c4 = (idx & 7) * 4;
            int gr = row0 + row;
            paf[r] = make_float4(0.f, 0.f, 0.f, 0.f);
            if (gr < Nn) paf[r] = *(const float4*)(Aext + (size_t)gr * K + c4);
        }
    } else {
        #pragma unroll
        for (int r = 0; r < 2; r++) {
            int idx = r * 256 + tid;
            int row = idx >> 2, c8 = (idx & 3) * 8;
            int gr = row0 + row;
            pau[r] = make_uint4(0u, 0u, 0u, 0u);
            if (gr < Nn) pau[r] = *(const uint4*)(g_h1h + (size_t)gr * K + c8);
        }
    }
    #pragma unroll
    for (int r = 0; r < 2; r++) {
        int idx = r * 256 + tid;
        int kr = idx >> 4, c8 = (idx & 15) * 8;
        pbu[r] = *(const uint4*)(Wh + (size_t)kr * HD + col0 + c8);
    }

    for (int k0 = 0; k0 < K; k0 += 32) {
        // deposit prefetched A tile
        if constexpr (ASEL == 0) {
            #pragma unroll
            for (int r = 0; r < 4; r++) {
                int idx = r * 256 + tid;
                int row = idx >> 3, c4 = (idx & 7) * 4;
                __nv_bfloat162 p0 = __float22bfloat162_rn(make_float2(paf[r].x, paf[r].y));
                __nv_bfloat162 p1 = __float22bfloat162_rn(make_float2(paf[r].z, paf[r].w));
                uint2 u;
                u.x = *(uint32_t*)&p0; u.y = *(uint32_t*)&p1;
                *(uint2*)&As[row][c4] = u;
            }
        } else {
            #pragma unroll
            for (int r = 0; r < 2; r++) {
                int idx = r * 256 + tid;
                int row = idx >> 2, c8 = (idx & 3) * 8;
                *(uint4*)&As[row][c8] = pau[r];
            }
        }
        // deposit prefetched B tile (already bf16)
        #pragma unroll
        for (int r = 0; r < 2; r++) {
            int idx = r * 256 + tid;
            int kr = idx >> 4, c8 = (idx & 15) * 8;
            *(uint4*)&Bs[kr][c8] = pbu[r];
        }
        __syncthreads();

        // issue next-tile loads BEFORE compute (overlap global latency w/ MMA)
        int kn = k0 + 32;
        if (kn < K) {
            if constexpr (ASEL == 0) {
                #pragma unroll
                for (int r = 0; r < 4; r++) {
                    int idx = r * 256 + tid;
                    int row = idx >> 3, c4 = (idx & 7) * 4;
                    int gr = row0 + row;
                    paf[r] = make_float4(0.f, 0.f, 0.f, 0.f);
                    if (gr < Nn) paf[r] = *(const float4*)(Aext + (size_t)gr * K + kn + c4);
                }
            } else {
                #pragma unroll
                for (int r = 0; r < 2; r++) {
                    int idx = r * 256 + tid;
                    int row = idx >> 2, c8 = (idx & 3) * 8;
                    int gr = row0 + row;
                    pau[r] = make_uint4(0u, 0u, 0u, 0u);
                    if (gr < Nn) pau[r] = *(const uint4*)(g_h1h + (size_t)gr * K + kn + c8);
                }
            }
            #pragma unroll
            for (int r = 0; r < 2; r++) {
                int idx = r * 256 + tid;
                int kr = idx >> 4, c8 = (idx & 15) * 8;
                pbu[r] = *(const uint4*)(Wh + (size_t)(kn + kr) * HD + col0 + c8);
            }
        }

        #pragma unroll
        for (int ks = 0; ks < 2; ks++) {
            uint32_t a[2][4];
            #pragma unroll
            for (int mt = 0; mt < 2; mt++)
                ldsm_x4(a[mt], aAddrBase[mt] + ks * 32);
            #pragma unroll
            for (int nt = 0; nt < 8; nt++) {
                int nb = wn * 64 + nt * 8;
                uint32_t b0, b1;
                ldsm_x2t(b0, b1, bAddrBase + (uint32_t)(ks * 16 * 272 + nb * 2));
                #pragma unroll
                for (int mt = 0; mt < 2; mt++)
                    mma_bf16(acc[mt][nt], a[mt], b0, b1);
            }
        }
        __syncthreads();
    }

    // ---- store z as bf16 ----
    #pragma unroll
    for (int mt = 0; mt < 2; mt++) {
        #pragma unroll
        for (int nt = 0; nt < 8; nt++) {
            int r = row0 + wm * 32 + mt * 16 + lr;
            int c = col0 + wn * 64 + nt * 8 + lc * 2;
            if (r < Nn)
                *(__nv_bfloat162*)&g_zh[(size_t)r * HD + c] =
                    __float22bfloat162_rn(make_float2(acc[mt][nt][0], acc[mt][nt][1]));
            if (r + 8 < Nn)
                *(__nv_bfloat162*)&g_zh[(size_t)(r + 8) * HD + c] =
                    __float22bfloat162_rn(make_float2(acc[mt][nt][2], acc[mt][nt][3]));
        }
    }

    // ---- fused el/er ----
    int head_base = (col0 >> 5) + wn * 2;
    float alc[2][8], arc[2][8];
    #pragma unroll
    for (int hs = 0; hs < 2; hs++)
        #pragma unroll
        for (int q = 0; q < 4; q++) {
            int d0 = q * 8 + lc * 2;
            int hg = head_base + hs;
            alc[hs][q * 2]     = al[hg * 32 + d0];
            alc[hs][q * 2 + 1] = al[hg * 32 + d0 + 1];
            arc[hs][q * 2]     = ar[hg * 32 + d0];
            arc[hs][q * 2 + 1] = ar[hg * 32 + d0 + 1];
        }
    float pel[4][2], per_[4][2];
    #pragma unroll
    for (int rs = 0; rs < 4; rs++)
        #pragma unroll
        for (int hs = 0; hs < 2; hs++) { pel[rs][hs] = 0.f; per_[rs][hs] = 0.f; }
    #pragma unroll
    for (int mt = 0; mt < 2; mt++)
        #pragma unroll
        for (int nt = 0; nt < 8; nt++) {
            int hs = nt >> 2, q = nt & 3;
            #pragma unroll
            for (int j = 0; j < 4; j++) {
                int rs = mt * 2 + (j >> 1);
                float a = acc[mt][nt][j];
                pel[rs][hs]  = fmaf(a, alc[hs][q * 2 + (j & 1)], pel[rs][hs]);
                per_[rs][hs] = fmaf(a, arc[hs][q * 2 + (j & 1)], per_[rs][hs]);
            }
        }
    #pragma unroll
    for (int rs = 0; rs < 4; rs++)
        #pragma unroll
        for (int hs = 0; hs < 2; hs++) {
            float v = pel[rs][hs], w = per_[rs][hs];
            v += __shfl_xor_sync(0xFFFFFFFFu, v, 1);
            v += __shfl_xor_sync(0xFFFFFFFFu, v, 2);
            w += __shfl_xor_sync(0xFFFFFFFFu, w, 1);
            w += __shfl_xor_sync(0xFFFFFFFFu, w, 2);
            if (lc == 0) {
                int r = row0 + wm * 32 + (rs >> 1) * 16 + (rs & 1) * 8 + lr;
                if (r < Nn) {
                    g_el[r * 8 + head_base + hs] = v;
                    g_er[r * 8 + head_base + hs] = w;
                }
            }
        }
}

// ------- warp-per-node aggregation: smem-staged weights, 4-edge unroll -----
// out_sel=1: write bf16 h1 (+relu). out_sel=0: write bf16 h2.
__device__ __forceinline__ void agg_step(float* acc, float w, const uint4& raw) {
    float2 f0 = __bfloat1622float2(*(const __nv_bfloat162*)&raw.x);
    float2 f1 = __bfloat1622float2(*(const __nv_bfloat162*)&raw.y);
    float2 f2 = __bfloat1622float2(*(const __nv_bfloat162*)&raw.z);
    float2 f3 = __bfloat1622float2(*(const __nv_bfloat162*)&raw.w);
    acc[0] = fmaf(w, f0.x, acc[0]); acc[1] = fmaf(w, f0.y, acc[1]);
    acc[2] = fmaf(w, f1.x, acc[2]); acc[3] = fmaf(w, f1.y, acc[3]);
    acc[4] = fmaf(w, f2.x, acc[4]); acc[5] = fmaf(w, f2.y, acc[5]);
    acc[6] = fmaf(w, f3.x, acc[6]); acc[7] = fmaf(w, f3.y, acc[7]);
}

__global__ __launch_bounds__(256) void k_agg(const float* __restrict__ bias,
                                             int out_sel) {
    __shared__ float sw[8][32][8];
    int gw = (blockIdx.x * blockDim.x + threadIdx.x) >> 5;
    if (gw >= Nn) return;
    int lane = threadIdx.x & 31;
    int wloc = threadIdx.x >> 5;
    int s0 = g_rowoff[gw], s1 = g_rowoff[gw + 1];

    float acc[8];
    #pragma unroll
    for (int k = 0; k < 8; k++) acc[k] = 0.f;
    float smv = 0.f;

    if (s1 > s0) {
        float4 erA = *(const float4*)(g_er + (size_t)gw * 8);
        float4 erB = *(const float4*)(g_er + (size_t)gw * 8 + 4);
        float er8[8] = {erA.x, erA.y, erA.z, erA.w, erB.x, erB.y, erB.z, erB.w};

        for (int base = s0; base < s1; base += 32) {
            int idx = base + lane;
            int cnt = min(32, s1 - base);
            int sn_l = (idx < s1) ? g_esrc[idx] : 0;
            // ---- phase A: lane-parallel weight computation ----
            if (idx < s1) {
                float4 e0 = *(const float4*)(g_el + (size_t)sn_l * 8);
                float4 e1 = *(const float4*)(g_el + (size_t)sn_l * 8 + 4);
                float ev[8] = {e0.x + er8[0], e0.y + er8[1], e0.z + er8[2], e0.w + er8[3],
                               e1.x + er8[4], e1.y + er8[5], e1.z + er8[6], e1.w + er8[7]};
                float wv[8];
                #pragma unroll
                for (int k = 0; k < 8; k++) {
                    float t = ev[k] > 0.f ? ev[k] : SLOPE * ev[k];
                    wv[k] = __expf(t);
                }
                *(float4*)&sw[wloc][lane][0] = make_float4(wv[0], wv[1], wv[2], wv[3]);
                *(float4*)&sw[wloc][lane][4] = make_float4(wv[4], wv[5], wv[6], wv[7]);
            }
            __syncwarp();
            // ---- phase B: gather + accumulate, 4-edge unroll (MLP=4) ----
            int hsel = lane >> 2;
            int j = 0;
            for (; j + 4 <= cnt; j += 4) {
                int sn0 = __shfl_sync(0xFFFFFFFFu, sn_l, j);
                int sn1 = __shfl_sync(0xFFFFFFFFu, sn_l, j + 1);
                int sn2 = __shfl_sync(0xFFFFFFFFu, sn_l, j + 2);
                int sn3 = __shfl_sync(0xFFFFFFFFu, sn_l, j + 3);
                uint4 r0 = *(const uint4*)(g_zh + (size_t)sn0 * HD + lane * 8);
                uint4 r1 = *(const uint4*)(g_zh + (size_t)sn1 * HD + lane * 8);
                uint4 r2 = *(const uint4*)(g_zh + (size_t)sn2 * HD + lane * 8);
                uint4 r3 = *(const uint4*)(g_zh + (size_t)sn3 * HD + lane * 8);
                float w0 = sw[wloc][j][hsel];
                float w1 = sw[wloc][j + 1][hsel];
                float w2 = sw[wloc][j + 2][hsel];
                float w3 = sw[wloc][j + 3][hsel];
                smv += (w0 + w1) + (w2 + w3);
                agg_step(acc, w0, r0);
                agg_step(acc, w1, r1);
                agg_step(acc, w2, r2);
                agg_step(acc, w3, r3);
            }
            for (; j + 2 <= cnt; j += 2) {
                int sn0 = __shfl_sync(0xFFFFFFFFu, sn_l, j);
                int sn1 = __shfl_sync(0xFFFFFFFFu, sn_l, j + 1);
                uint4 r0 = *(const uint4*)(g_zh + (size_t)sn0 * HD + lane * 8);
                uint4 r1 = *(const uint4*)(g_zh + (size_t)sn1 * HD + lane * 8);
                float w0 = sw[wloc][j][hsel];
                float w1 = sw[wloc][j + 1][hsel];
                smv += w0 + w1;
                agg_step(acc, w0, r0);
                agg_step(acc, w1, r1);
            }
            if (j < cnt) {
                int sn = __shfl_sync(0xFFFFFFFFu, sn_l, j);
                float wv = sw[wloc][j][hsel];
                smv += wv;
                uint4 raw = *(const uint4*)(g_zh + (size_t)sn * HD + lane * 8);
                agg_step(acc, wv, raw);
            }
            __syncwarp();
        }
        float inv = __frcp_rn(smv);
        #pragma unroll
        for (int k = 0; k < 8; k++) acc[k] *= inv;
    }

    const float* bp = bias + lane * 8;
    float o[8];
    #pragma unroll
    for (int k = 0; k < 8; k++) o[k] = acc[k] + bp[k];

    if (out_sel) {
        #pragma unroll
        for (int k = 0; k < 8; k++) o[k] = fmaxf(o[k], 0.f);
    }
    __nv_bfloat16* dst = (out_sel ? g_h1h : g_h2h) + (size_t)gw * HD + lane * 8;
    __nv_bfloat162 q0 = __float22bfloat162_rn(make_float2(o[0], o[1]));
    __nv_bfloat162 q1 = __float22bfloat162_rn(make_float2(o[2], o[3]));
    __nv_bfloat162 q2 = __float22bfloat162_rn(make_float2(o[4], o[5]));
    __nv_bfloat162 q3 = __float22bfloat162_rn(make_float2(o[6], o[7]));
    uint4 u;
    u.x = *(uint32_t*)&q0; u.y = *(uint32_t*)&q1;
    u.z = *(uint32_t*)&q2; u.w = *(uint32_t*)&q3;
    *(uint4*)dst = u;
}

// ---------------- readout --------------------------------------------------
__global__ void k_gbound_zero(const int* __restrict__ gid) {
    int t = blockIdx.x * blockDim.x + threadIdx.x;
    if (t < Bb * HD) g_hg[t] = 0.f;
    if (blockIdx.x == 0 && threadIdx.x <= Bb) {
        int g = threadIdx.x;
        int lo = 0, hi = Nn;
        while (lo < hi) {
            int mid = (lo + hi) >> 1;
            if (gid[mid] < g) lo = mid + 1;
            else hi = mid;
        }
        g_gbound[g] = lo;
    }
}

__global__ void k_mean_part() {  // grid=(Bb,8), block=HD
    int b = blockIdx.x, d = threadIdx.x;
    int s = g_gbound[b], e = g_gbound[b + 1];
    float sum = 0.f;
    for (int n = s + blockIdx.y; n < e; n += 8)
        sum += __bfloat162float(g_h2h[(size_t)n * HD + d]);
    atomicAdd(&g_hg[b * HD + d], sum);
}

__global__ void k_cls(const float* __restrict__ perm, const float* __restrict__ Wc,
                      const float* __restrict__ bc, float* __restrict__ out) {
    int t = blockIdx.x * blockDim.x + threadIdx.x;
    if (t >= Bb * Cc) return;
    int b = t / Cc, c = t % Cc;
    int cnt = g_gbound[b + 1] - g_gbound[b];
    float inv = 1.f / (float)(cnt > 0 ? cnt : 1);
    float sg = 0.f;
    #pragma unroll 4
    for (int i = 0; i < HD; i++) sg = fmaf(g_hg[b * HD + i], Wc[i * Cc + c], sg);
    float s = bc[c] + sg * inv;
    #pragma unroll 4
    for (int i = 0; i < PERMD; i++)
        s = fmaf(perm[b * PERMD + i], Wc[(HD + i) * Cc + c], s);
    out[t] = s;
}

// ---------------- launch: fork CSR chain onto a side stream ----------------
extern "C" void kernel_launch(void* const* d_in, const int* in_sizes, int n_in,
                              void* d_out, int out_size) {
    const float* h    = (const float*)d_in[0];
    const float* perm = (const float*)d_in[1];
    const float* W1   = (const float*)d_in[2];
    const float* al1  = (const float*)d_in[3];
    const float* ar1  = (const float*)d_in[4];
    const float* b1   = (const float*)d_in[5];
    const float* W2   = (const float*)d_in[6];
    const float* al2  = (const float*)d_in[7];
    const float* ar2  = (const float*)d_in[8];
    const float* b2   = (const float*)d_in[9];
    const float* Wc   = (const float*)d_in[10];
    const float* bc   = (const float*)d_in[11];
    const int*   src  = (const int*)d_in[12];
    const int*   dstv = (const int*)d_in[13];
    const int*   gid  = (const int*)d_in[14];
    float* out = (float*)d_out;

    cudaStream_t s0 = (cudaStream_t)0;       // capture-origin (legacy) stream
    cudaStream_t s2;
    cudaStreamCreateWithFlags(&s2, cudaStreamNonBlocking);
    cudaEvent_t eFork, eCsr, eGb;
    cudaEventCreateWithFlags(&eFork, cudaEventDisableTiming);
    cudaEventCreateWithFlags(&eCsr, cudaEventDisableTiming);
    cudaEventCreateWithFlags(&eGb, cudaEventDisableTiming);

    // fork side stream off the origin stream (capture-legal pattern)
    cudaEventRecord(eFork, s0);
    cudaStreamWaitEvent(s2, eFork, 0);

    // side stream: CSR build (needs only src/dst) + graph boundaries
    k_zero_counts<<<(Nn + 255) / 256, 256, 0, s2>>>();
    k_count<<<(En + 255) / 256, 256, 0, s2>>>(dstv);
    k_bsum<<<49, 1024, 0, s2>>>();
    k_scan2<<<49, 1024, 0, s2>>>();
    k_scatter<<<(En + 255) / 256, 256, 0, s2>>>(src, dstv);
    cudaEventRecord(eCsr, s2);
    k_gbound_zero<<<(Bb * HD + 255) / 256, 256, 0, s2>>>(gid);
    cudaEventRecord(eGb, s2);

    dim3 gemm_grid(HD / 128, (Nn + 127) / 128);
    int node_warp_blocks = (Nn * 32 + 255) / 256;

    // main stream: weight pre-conversion (once), then layer-1 GEMM overlapping CSR
    k_wconv<<<(HD * HD + 255) / 256, 256, 0, s0>>>(W1, W2);
    k_gemm_bf16<0><<<gemm_grid, 256, 0, s0>>>(h, al1, ar1, IN_DIM);
    cudaStreamWaitEvent(s0, eCsr, 0);        // join: agg needs rowoff/esrc
    k_agg<<<node_warp_blocks, 256, 0, s0>>>(b1, /*out=h1 bf16*/1);

    // layer 2 (A = bf16 g_h1h, W = bf16 g_w2h — selected inside kernel)
    k_gemm_bf16<1><<<gemm_grid, 256, 0, s0>>>(nullptr, al2, ar2, HD);
    k_agg<<<node_warp_blocks, 256, 0, s0>>>(b2, /*out=h2 bf16*/0);

    // readout
    cudaStreamWaitEvent(s0, eGb, 0);         // join: mean needs g_hg/gbound
    k_mean_part<<<dim3(Bb, 8), HD, 0, s0>>>();
    k_cls<<<(Bb * Cc + 127) / 128, 128, 0, s0>>>(perm, Wc, bc, out);

    cudaEventDestroy(eFork);
    cudaEventDestroy(eCsr);
    cudaEventDestroy(eGb);
    cudaStreamDestroy(s2);
}